// round 2
// baseline (speedup 1.0000x reference)
#include <cuda_runtime.h>
#include <math.h>

#define NNODES 10000
#define NEDGES 160000
#define DDIM   512

// Scratch (no allocations allowed in kernel_launch)
__device__ float g_agg[(size_t)NNODES * DDIM];
__device__ float g_deg[NNODES];
__device__ float g_invdeg[NNODES];
__device__ int   g_ei_is64;

// ---------------------------------------------------------------------------
// Kernel 0: detect edge_index dtype. int64 values < 2^31 viewed as int32 have
// zero high words at all odd indices. Deterministic for fixed input.
// ---------------------------------------------------------------------------
__global__ void detect_kernel(const int* __restrict__ ei32) {
    if (threadIdx.x == 0 && blockIdx.x == 0) {
        int acc = 0;
#pragma unroll
        for (int i = 1; i < 32; i += 2) acc |= ei32[i];
        g_ei_is64 = (acc == 0) ? 1 : 0;
    }
}

// ---------------------------------------------------------------------------
// Kernel 1: zero the aggregation scratch + degree counters
// ---------------------------------------------------------------------------
__global__ void zero_kernel() {
    const int stride = gridDim.x * blockDim.x;
    for (int i = blockIdx.x * blockDim.x + threadIdx.x;
         i < NNODES * DDIM; i += stride) {
        g_agg[i] = 0.0f;
    }
    for (int i = blockIdx.x * blockDim.x + threadIdx.x;
         i < NNODES; i += stride) {
        g_deg[i] = 0.0f;
    }
}

// ---------------------------------------------------------------------------
// Kernel 2: edge scatter-add. One warp per edge: gather x[src] (float4,
// coalesced, mostly L2-resident) and atomicAdd into g_agg[dst].
// ---------------------------------------------------------------------------
__global__ __launch_bounds__(256) void scatter_kernel(
    const void* __restrict__ edge_index,        // [2, NEDGES] int32 or int64
    const float* __restrict__ x)                // [NNODES, DDIM]
{
    const int warp = (blockIdx.x * blockDim.x + threadIdx.x) >> 5;
    const int lane = threadIdx.x & 31;
    if (warp >= NEDGES) return;

    int src, dst;
    if (g_ei_is64) {
        const long long* e64 = (const long long*)edge_index;
        src = (int)e64[warp];
        dst = (int)e64[NEDGES + warp];
    } else {
        const int* e32 = (const int*)edge_index;
        src = e32[warp];
        dst = e32[NEDGES + warp];
    }
    // Defensive: surface contract mismatches as wrong answers, not crashes.
    if ((unsigned)src >= NNODES || (unsigned)dst >= NNODES) return;

    const float4* xs = (const float4*)(x + (size_t)src * DDIM);
    float* ag = g_agg + (size_t)dst * DDIM;

    if (lane == 0) atomicAdd(&g_deg[dst], 1.0f);

#pragma unroll
    for (int j = 0; j < 4; ++j) {
        const int c = lane + 32 * j;           // float4 index 0..127
        const float4 v = xs[c];
        float* p = ag + c * 4;
        atomicAdd(p + 0, v.x);
        atomicAdd(p + 1, v.y);
        atomicAdd(p + 2, v.z);
        atomicAdd(p + 3, v.w);
    }
}

// ---------------------------------------------------------------------------
// Kernel 3: inv-degree
// ---------------------------------------------------------------------------
__global__ void invdeg_kernel() {
    const int i = blockIdx.x * blockDim.x + threadIdx.x;
    if (i < NNODES) g_invdeg[i] = 1.0f / fmaxf(g_deg[i], 1.0f);
}

// ---------------------------------------------------------------------------
// Kernel 4: fused GEMM + bias + swish.
//   out = swish( [agg*invdeg | x] (10000 x 1024) @ [W_l ; W_r] (1024 x 512) + b )
// Classic 128x128 block tile, BK=8, 256 threads, 8x8 micro-tile per thread.
// ---------------------------------------------------------------------------
__global__ __launch_bounds__(256) void sage_gemm_kernel(
    const float* __restrict__ x,
    const float* __restrict__ Wl,   // [512, 512] row-major (K x N)
    const float* __restrict__ Wr,   // [512, 512]
    const float* __restrict__ bias, // [512]
    float* __restrict__ out)        // [NNODES, 512]
{
    __shared__ float As[8][128];   // transposed A tile: As[k][m]
    __shared__ float Bs[8][128];   // Bs[k][n]

    const int tid = threadIdx.x;
    const int rowBase = blockIdx.x * 128;
    const int colBase = blockIdx.y * 128;

    const int tr = tid >> 4;            // 0..15, M micro-tile
    const int tc = tid & 15;            // 0..15, N micro-tile

    const int innerRowA = tid >> 1;         // 0..127
    const int innerColA = (tid & 1) * 4;    // 0 or 4
    const int innerRowB = tid >> 5;         // 0..7
    const int innerColB = (tid & 31) * 4;   // 0..124

    float acc[8][8];
#pragma unroll
    for (int i = 0; i < 8; ++i)
#pragma unroll
        for (int j = 0; j < 8; ++j) acc[i][j] = 0.0f;

    const int aRow = rowBase + innerRowA;
    const bool aValid = (aRow < NNODES);
    const float invd = aValid ? g_invdeg[aRow] : 0.0f;

    for (int k0 = 0; k0 < 1024; k0 += 8) {
        // ---- load A tile (virtual concat [mean | x]) ----
        float4 av = make_float4(0.f, 0.f, 0.f, 0.f);
        if (aValid) {
            if (k0 < 512) {
                const float4 t = *(const float4*)(g_agg + (size_t)aRow * DDIM + k0 + innerColA);
                av.x = t.x * invd; av.y = t.y * invd;
                av.z = t.z * invd; av.w = t.w * invd;
            } else {
                av = *(const float4*)(x + (size_t)aRow * DDIM + (k0 - 512) + innerColA);
            }
        }
        As[innerColA + 0][innerRowA] = av.x;
        As[innerColA + 1][innerRowA] = av.y;
        As[innerColA + 2][innerRowA] = av.z;
        As[innerColA + 3][innerRowA] = av.w;

        // ---- load B tile (virtual stack [W_l ; W_r]) ----
        float4 bv;
        if (k0 < 512)
            bv = *(const float4*)(Wl + (size_t)(k0 + innerRowB) * 512 + colBase + innerColB);
        else
            bv = *(const float4*)(Wr + (size_t)(k0 - 512 + innerRowB) * 512 + colBase + innerColB);
        *(float4*)&Bs[innerRowB][innerColB] = bv;

        __syncthreads();

        float aReg[8], bReg[8];
#pragma unroll
        for (int kk = 0; kk < 8; ++kk) {
            *(float4*)&aReg[0] = *(const float4*)&As[kk][tr * 8];
            *(float4*)&aReg[4] = *(const float4*)&As[kk][tr * 8 + 4];
            *(float4*)&bReg[0] = *(const float4*)&Bs[kk][tc * 8];
            *(float4*)&bReg[4] = *(const float4*)&Bs[kk][tc * 8 + 4];
#pragma unroll
            for (int i = 0; i < 8; ++i)
#pragma unroll
                for (int j = 0; j < 8; ++j)
                    acc[i][j] += aReg[i] * bReg[j];
        }
        __syncthreads();
    }

    // ---- epilogue: bias + swish, vectorized store ----
    float bv[8];
#pragma unroll
    for (int j = 0; j < 8; ++j) bv[j] = bias[colBase + tc * 8 + j];

#pragma unroll
    for (int i = 0; i < 8; ++i) {
        const int row = rowBase + tr * 8 + i;
        if (row < NNODES) {
            float o[8];
#pragma unroll
            for (int j = 0; j < 8; ++j) {
                const float h = acc[i][j] + bv[j];
                const float s = 1.0f / (1.0f + expf(-h));
                o[j] = h * s;
            }
            float4* po = (float4*)(out + (size_t)row * 512 + colBase + tc * 8);
            po[0] = *(const float4*)&o[0];
            po[1] = *(const float4*)&o[4];
        }
    }
}

// ---------------------------------------------------------------------------
extern "C" void kernel_launch(void* const* d_in, const int* in_sizes, int n_in,
                              void* d_out, int out_size) {
    // Identify inputs by element count (robust to metadata ordering).
    const float* x  = nullptr;
    const void*  ei = nullptr;
    const float* Wl = nullptr;
    const float* Wr = nullptr;
    const float* b  = nullptr;

    for (int i = 0; i < n_in; ++i) {
        const int s = in_sizes[i];
        if (s == NNODES * DDIM)      x  = (const float*)d_in[i];
        else if (s == 2 * NEDGES)    ei = d_in[i];
        else if (s == DDIM * DDIM) { if (!Wl) Wl = (const float*)d_in[i];
                                     else     Wr = (const float*)d_in[i]; }
        else if (s == DDIM)          b  = (const float*)d_in[i];
    }
    float* out = (float*)d_out;
    (void)out_size;

    // 0) detect edge_index dtype (int32 vs int64)
    detect_kernel<<<1, 32>>>((const int*)ei);

    // 1) zero scratch
    zero_kernel<<<512, 256>>>();

    // 2) scatter-add: one warp per edge, 8 warps per block
    const int edgesPerBlock = 256 / 32;
    scatter_kernel<<<(NEDGES + edgesPerBlock - 1) / edgesPerBlock, 256>>>(ei, x);

    // 3) inverse degree
    invdeg_kernel<<<(NNODES + 255) / 256, 256>>>();

    // 4) fused GEMM + bias + swish
    dim3 grid((NNODES + 127) / 128, 512 / 128);
    sage_gemm_kernel<<<grid, 256>>>(x, Wl, Wr, b, out);
}

// round 4
// speedup vs baseline: 1.8118x; 1.8118x over previous
#include <cuda_runtime.h>
#include <cuda_bf16.h>
#include <math.h>
#include <cstdint>

#define NNODES 10000
#define NEDGES 160000
#define DDIM   512
#define KTOT   1024
#define MPAD   10112              // 79 * 128
#define MTILES 79
#define NTILES 4
#define KCHUNK 32
#define NSTAGE 3
#define KSTEPS (KTOT / KCHUNK)    // 32 chunks of K=32

// smem tile: 128 rows x 32 bf16, row stride 80B (64B data + 16B pad)
#define ROWB        80
#define TILE_BYTES  (128 * ROWB)          // 10240
#define STAGE_BYTES (4 * TILE_BYTES)      // Ahi|Alo|Bhi|Blo = 40960
#define SMEM_TOTAL  (NSTAGE * STAGE_BYTES) // 122880

// ---------------------------------------------------------------------------
// Device scratch
// ---------------------------------------------------------------------------
__device__ float g_agg[(size_t)NNODES * DDIM];
__device__ float g_deg[NNODES];
__device__ float g_invdeg[NNODES];
__device__ int   g_ei_is64;
__device__ __nv_bfloat16 g_Ahi[(size_t)MPAD * KTOT];
__device__ __nv_bfloat16 g_Alo[(size_t)MPAD * KTOT];
__device__ __nv_bfloat16 g_Bhi[(size_t)DDIM * KTOT];   // [n][k]
__device__ __nv_bfloat16 g_Blo[(size_t)DDIM * KTOT];

// ---------------------------------------------------------------------------
// helpers
// ---------------------------------------------------------------------------
__device__ __forceinline__ uint32_t smem_u32(const void* p) {
    uint32_t a;
    asm("{ .reg .u64 t; cvta.to.shared.u64 t, %1; cvt.u32.u64 %0, t; }"
        : "=r"(a) : "l"(p));
    return a;
}
#define CP16(sm, gm) \
    asm volatile("cp.async.cg.shared.global [%0], [%1], 16;" :: "r"(sm), "l"(gm))
#define CP_COMMIT() asm volatile("cp.async.commit_group;" ::: "memory")
#define CP_WAIT2()  asm volatile("cp.async.wait_group 2;"  ::: "memory")

#define LDMX4(r0, r1, r2, r3, addr) \
    asm volatile("ldmatrix.sync.aligned.m8n8.x4.shared.b16 {%0,%1,%2,%3}, [%4];" \
        : "=r"(r0), "=r"(r1), "=r"(r2), "=r"(r3) : "r"(addr))

__device__ __forceinline__ void mma_bf16(float* c, const uint32_t* a,
                                         const uint32_t* b) {
    asm volatile(
        "mma.sync.aligned.m16n8k16.row.col.f32.bf16.bf16.f32 "
        "{%0,%1,%2,%3}, {%4,%5,%6,%7}, {%8,%9}, {%0,%1,%2,%3};"
        : "+f"(c[0]), "+f"(c[1]), "+f"(c[2]), "+f"(c[3])
        : "r"(a[0]), "r"(a[1]), "r"(a[2]), "r"(a[3]), "r"(b[0]), "r"(b[1]));
}

// ---------------------------------------------------------------------------
// Kernel 0: detect edge_index dtype (int64 -> odd int32 words all zero)
// ---------------------------------------------------------------------------
__global__ void detect_kernel(const int* __restrict__ ei32) {
    if (threadIdx.x == 0 && blockIdx.x == 0) {
        int acc = 0;
#pragma unroll
        for (int i = 1; i < 32; i += 2) acc |= ei32[i];
        g_ei_is64 = (acc == 0) ? 1 : 0;
    }
}

// ---------------------------------------------------------------------------
// Kernel 1: zero scratch
// ---------------------------------------------------------------------------
__global__ void zero_kernel() {
    const int stride = gridDim.x * blockDim.x;
    float4* ag4 = (float4*)g_agg;
    for (int i = blockIdx.x * blockDim.x + threadIdx.x;
         i < NNODES * DDIM / 4; i += stride)
        ag4[i] = make_float4(0.f, 0.f, 0.f, 0.f);
    for (int i = blockIdx.x * blockDim.x + threadIdx.x; i < NNODES; i += stride)
        g_deg[i] = 0.0f;
}

// ---------------------------------------------------------------------------
// Kernel 2: edge scatter-add (warp per edge)
// ---------------------------------------------------------------------------
__global__ __launch_bounds__(256) void scatter_kernel(
    const void* __restrict__ edge_index, const float* __restrict__ x)
{
    const int warp = (blockIdx.x * blockDim.x + threadIdx.x) >> 5;
    const int lane = threadIdx.x & 31;
    if (warp >= NEDGES) return;

    int src, dst;
    if (g_ei_is64) {
        const long long* e64 = (const long long*)edge_index;
        src = (int)e64[warp];
        dst = (int)e64[NEDGES + warp];
    } else {
        const int* e32 = (const int*)edge_index;
        src = e32[warp];
        dst = e32[NEDGES + warp];
    }
    if ((unsigned)src >= NNODES || (unsigned)dst >= NNODES) return;

    const float4* xs = (const float4*)(x + (size_t)src * DDIM);
    float* ag = g_agg + (size_t)dst * DDIM;
    if (lane == 0) atomicAdd(&g_deg[dst], 1.0f);

#pragma unroll
    for (int j = 0; j < 4; ++j) {
        const int c = lane + 32 * j;
        const float4 v = xs[c];
        float* p = ag + c * 4;
        atomicAdd(p + 0, v.x);
        atomicAdd(p + 1, v.y);
        atomicAdd(p + 2, v.z);
        atomicAdd(p + 3, v.w);
    }
}

// ---------------------------------------------------------------------------
// Kernel 3: inv-degree
// ---------------------------------------------------------------------------
__global__ void invdeg_kernel() {
    const int i = blockIdx.x * blockDim.x + threadIdx.x;
    if (i < NNODES) g_invdeg[i] = 1.0f / fmaxf(g_deg[i], 1.0f);
}

// ---------------------------------------------------------------------------
// Kernel 4: A = [agg*invdeg | x] -> bf16 hi/lo, zero-padded to MPAD rows
// ---------------------------------------------------------------------------
__global__ __launch_bounds__(256) void convertA_kernel(const float* __restrict__ x) {
    const int i = blockIdx.x * blockDim.x + threadIdx.x;
    if (i >= MPAD * (KTOT / 4)) return;
    const int row = i >> 8;
    const int g   = (i & 255) * 4;

    float4 v = make_float4(0.f, 0.f, 0.f, 0.f);
    if (row < NNODES) {
        if (g < DDIM) {
            v = *(const float4*)(g_agg + (size_t)row * DDIM + g);
            const float d = g_invdeg[row];
            v.x *= d; v.y *= d; v.z *= d; v.w *= d;
        } else {
            v = *(const float4*)(x + (size_t)row * DDIM + (g - DDIM));
        }
    }
    __nv_bfloat162 h01 = __float22bfloat162_rn(make_float2(v.x, v.y));
    __nv_bfloat162 h23 = __float22bfloat162_rn(make_float2(v.z, v.w));
    __nv_bfloat162 l01 = __float22bfloat162_rn(make_float2(
        v.x - __bfloat162float(__low2bfloat16(h01)),
        v.y - __bfloat162float(__high2bfloat16(h01))));
    __nv_bfloat162 l23 = __float22bfloat162_rn(make_float2(
        v.z - __bfloat162float(__low2bfloat16(h23)),
        v.w - __bfloat162float(__high2bfloat16(h23))));

    *(__nv_bfloat162*)(g_Ahi + (size_t)row * KTOT + g)     = h01;
    *(__nv_bfloat162*)(g_Ahi + (size_t)row * KTOT + g + 2) = h23;
    *(__nv_bfloat162*)(g_Alo + (size_t)row * KTOT + g)     = l01;
    *(__nv_bfloat162*)(g_Alo + (size_t)row * KTOT + g + 2) = l23;
}

// ---------------------------------------------------------------------------
// Kernel 5: B[n][k] = W[k][n] (W=[Wl;Wr]) -> bf16 hi/lo transposed
// ---------------------------------------------------------------------------
__global__ __launch_bounds__(256) void convertB_kernel(
    const float* __restrict__ Wl, const float* __restrict__ Wr)
{
    const int i = blockIdx.x * blockDim.x + threadIdx.x;
    if (i >= KTOT * DDIM) return;
    const int k = i >> 9;
    const int n = i & 511;
    const float w = (k < DDIM) ? Wl[(size_t)k * DDIM + n]
                               : Wr[(size_t)(k - DDIM) * DDIM + n];
    const __nv_bfloat16 hi = __float2bfloat16(w);
    const __nv_bfloat16 lo = __float2bfloat16(w - __bfloat162float(hi));
    g_Bhi[(size_t)n * KTOT + k] = hi;
    g_Blo[(size_t)n * KTOT + k] = lo;
}

// ---------------------------------------------------------------------------
// Kernel 6: HMMA GEMM (mma.sync bf16, split hi/lo) + bias + swish
// ---------------------------------------------------------------------------
__device__ __forceinline__ void load_stage(
    uint32_t st, int k0, int mBase, int nBase, int tid)
{
#pragma unroll
    for (int i = 0; i < 8; ++i) {
        const int idx = tid + i * 256;          // 0..2047
        const int mat = idx >> 9;               // 0..3
        const int rem = idx & 511;
        const int row = rem >> 2;               // 0..127
        const int ch  = rem & 3;                // 16B chunk in row
        const uint32_t sm = st + mat * TILE_BYTES + row * ROWB + ch * 16;
        const __nv_bfloat16* gp;
        if      (mat == 0) gp = g_Ahi + (size_t)(mBase + row) * KTOT + k0 + ch * 8;
        else if (mat == 1) gp = g_Alo + (size_t)(mBase + row) * KTOT + k0 + ch * 8;
        else if (mat == 2) gp = g_Bhi + (size_t)(nBase + row) * KTOT + k0 + ch * 8;
        else               gp = g_Blo + (size_t)(nBase + row) * KTOT + k0 + ch * 8;
        CP16(sm, gp);
    }
}

__global__ __launch_bounds__(256, 1)
void gemm_kernel(const float* __restrict__ bias, float* __restrict__ out)
{
    extern __shared__ __align__(128) char smem[];
    const uint32_t smem_base = smem_u32(smem);
    const int tid   = threadIdx.x;
    const int wid   = tid >> 5;
    const int lane  = tid & 31;
    const int warpM = wid >> 2;         // 0..1  -> 64 rows
    const int warpN = wid & 3;          // 0..3  -> 32 cols
    const int mBase = blockIdx.x * 128;
    const int nBase = blockIdx.y * 128;

    float acc[4][4][4];
#pragma unroll
    for (int i = 0; i < 4; ++i)
#pragma unroll
        for (int j = 0; j < 4; ++j)
#pragma unroll
            for (int r = 0; r < 4; ++r) acc[i][j][r] = 0.0f;

    // prologue
#pragma unroll
    for (int s = 0; s < NSTAGE; ++s) {
        load_stage(smem_base + s * STAGE_BYTES, s * KCHUNK, mBase, nBase, tid);
        CP_COMMIT();
    }

    // per-lane ldmatrix address components
    const int matA = lane >> 3;          // 0..3
    const int rA   = lane & 7;
    const int rowA_off = ((matA & 1) << 3) + rA;      // row within m16 tile
    const int chA_off  = matA >> 1;                   // 0/1 -> k chunk
    const int rowB_off = ((matA >> 1) << 3) + rA;     // row within n16 pair
    const int chB_off  = matA & 1;

    for (int s = 0; s < KSTEPS; ++s) {
        CP_WAIT2();
        __syncthreads();

        const uint32_t st  = smem_base + (s % NSTAGE) * STAGE_BYTES;
        const uint32_t sAh = st;
        const uint32_t sAl = st + TILE_BYTES;
        const uint32_t sBh = st + 2 * TILE_BYTES;
        const uint32_t sBl = st + 3 * TILE_BYTES;

#pragma unroll
        for (int kk = 0; kk < 2; ++kk) {          // two k16 steps per chunk
            uint32_t ah[4][4], al[4][4], bh[4][2], bl[4][2];
#pragma unroll
            for (int mt = 0; mt < 4; ++mt) {
                const int row = warpM * 64 + mt * 16 + rowA_off;
                const int ch  = kk * 2 + chA_off;
                const uint32_t a = row * ROWB + ch * 16;
                LDMX4(ah[mt][0], ah[mt][1], ah[mt][2], ah[mt][3], sAh + a);
                LDMX4(al[mt][0], al[mt][1], al[mt][2], al[mt][3], sAl + a);
            }
#pragma unroll
            for (int p = 0; p < 2; ++p) {         // each pair = 2 n8 tiles
                const int row = warpN * 32 + p * 16 + rowB_off;
                const int ch  = kk * 2 + chB_off;
                const uint32_t a = row * ROWB + ch * 16;
                LDMX4(bh[2*p][0], bh[2*p][1], bh[2*p+1][0], bh[2*p+1][1], sBh + a);
                LDMX4(bl[2*p][0], bl[2*p][1], bl[2*p+1][0], bl[2*p+1][1], sBl + a);
            }
#pragma unroll
            for (int mt = 0; mt < 4; ++mt)
#pragma unroll
                for (int nt = 0; nt < 4; ++nt) {
                    mma_bf16(acc[mt][nt], ah[mt], bh[nt]);
                    mma_bf16(acc[mt][nt], ah[mt], bl[nt]);
                    mma_bf16(acc[mt][nt], al[mt], bh[nt]);
                }
        }

        __syncthreads();
        if (s + NSTAGE < KSTEPS)
            load_stage(st, (s + NSTAGE) * KCHUNK, mBase, nBase, tid);
        CP_COMMIT();
    }

    // epilogue: bias + swish
    const int colLane = (lane & 3) * 2;
    const int rowLane = lane >> 2;
#pragma unroll
    for (int mt = 0; mt < 4; ++mt) {
#pragma unroll
        for (int nt = 0; nt < 4; ++nt) {
            const int col = nBase + warpN * 32 + nt * 8 + colLane;
            const float b0 = __ldg(bias + col);
            const float b1 = __ldg(bias + col + 1);
#pragma unroll
            for (int half = 0; half < 2; ++half) {
                const int row = mBase + warpM * 64 + mt * 16 + rowLane + half * 8;
                if (row < NNODES) {
                    float h0 = acc[mt][nt][half * 2 + 0] + b0;
                    float h1 = acc[mt][nt][half * 2 + 1] + b1;
                    float2 o;
                    o.x = h0 / (1.0f + expf(-h0));
                    o.y = h1 / (1.0f + expf(-h1));
                    *(float2*)(out + (size_t)row * DDIM + col) = o;
                }
            }
        }
    }
}

// ---------------------------------------------------------------------------
extern "C" void kernel_launch(void* const* d_in, const int* in_sizes, int n_in,
                              void* d_out, int out_size) {
    const float* x  = nullptr;
    const void*  ei = nullptr;
    const float* Wl = nullptr;
    const float* Wr = nullptr;
    const float* b  = nullptr;

    for (int i = 0; i < n_in; ++i) {
        const int s = in_sizes[i];
        if (s == NNODES * DDIM)      x  = (const float*)d_in[i];
        else if (s == 2 * NEDGES)    ei = d_in[i];
        else if (s == DDIM * DDIM) { if (!Wl) Wl = (const float*)d_in[i];
                                     else     Wr = (const float*)d_in[i]; }
        else if (s == DDIM)          b  = (const float*)d_in[i];
    }
    float* out = (float*)d_out;
    (void)out_size;

    cudaFuncSetAttribute(gemm_kernel,
        cudaFuncAttributeMaxDynamicSharedMemorySize, SMEM_TOTAL);

    detect_kernel<<<1, 32>>>((const int*)ei);
    zero_kernel<<<512, 256>>>();

    const int edgesPerBlock = 256 / 32;
    scatter_kernel<<<(NEDGES + edgesPerBlock - 1) / edgesPerBlock, 256>>>(ei, x);
    invdeg_kernel<<<(NNODES + 255) / 256, 256>>>();

    convertA_kernel<<<(MPAD * (KTOT / 4) + 255) / 256, 256>>>(x);
    convertB_kernel<<<(KTOT * DDIM + 255) / 256, 256>>>(Wl, Wr);

    dim3 grid(MTILES, NTILES);
    gemm_kernel<<<grid, 256, SMEM_TOTAL>>>(b, out);
}

// round 5
// speedup vs baseline: 3.2657x; 1.8024x over previous
#include <cuda_runtime.h>
#include <cuda_bf16.h>
#include <math.h>
#include <cstdint>

#define NNODES 10000
#define NEDGES 160000
#define DDIM   512
#define KTOT   1024
#define MTILE  160
#define MTILES 64
#define MPAD   (MTILE * MTILES)   // 10240
#define NTILES 4
#define KCHUNK 32
#define NSTAGE 4
#define KSTEPS (KTOT / KCHUNK)    // 32

// smem: rows of 32 bf16, stride 80B (64B data + 16B pad) -> conflict-free LDSM
#define ROWB    80
#define A_TILEB (MTILE * ROWB)            // 12800
#define B_TILEB (128 * ROWB)              // 10240
#define OFF_AH  0
#define OFF_AL  (A_TILEB)
#define OFF_BH  (2 * A_TILEB)
#define OFF_BL  (2 * A_TILEB + B_TILEB)
#define STAGE_BYTES (2 * A_TILEB + 2 * B_TILEB)   // 46080
#define SMEM_TOTAL  (NSTAGE * STAGE_BYTES)        // 184320

// ---------------------------------------------------------------------------
// Device scratch
// ---------------------------------------------------------------------------
__device__ int   g_ei_is64;
__device__ int   g_degi[NNODES];
__device__ int   g_off[NNODES + 1];
__device__ int   g_cursor[NNODES];
__device__ int   g_elist[NEDGES];
__device__ __nv_bfloat16 g_Ahi[(size_t)MPAD * KTOT];
__device__ __nv_bfloat16 g_Alo[(size_t)MPAD * KTOT];
__device__ __nv_bfloat16 g_Bhi[(size_t)DDIM * KTOT];   // [n][k]
__device__ __nv_bfloat16 g_Blo[(size_t)DDIM * KTOT];

// ---------------------------------------------------------------------------
// helpers
// ---------------------------------------------------------------------------
__device__ __forceinline__ uint32_t smem_u32(const void* p) {
    uint32_t a;
    asm("{ .reg .u64 t; cvta.to.shared.u64 t, %1; cvt.u32.u64 %0, t; }"
        : "=r"(a) : "l"(p));
    return a;
}
#define CP16(sm, gm) \
    asm volatile("cp.async.cg.shared.global [%0], [%1], 16;" :: "r"(sm), "l"(gm))
#define CP_COMMIT() asm volatile("cp.async.commit_group;" ::: "memory")
#define CP_WAIT()   asm volatile("cp.async.wait_group 3;"  ::: "memory")

#define LDMX4(r0, r1, r2, r3, addr) \
    asm volatile("ldmatrix.sync.aligned.m8n8.x4.shared.b16 {%0,%1,%2,%3}, [%4];" \
        : "=r"(r0), "=r"(r1), "=r"(r2), "=r"(r3) : "r"(addr))

__device__ __forceinline__ void mma_bf16(float* c, const uint32_t* a,
                                         const uint32_t* b) {
    asm volatile(
        "mma.sync.aligned.m16n8k16.row.col.f32.bf16.bf16.f32 "
        "{%0,%1,%2,%3}, {%4,%5,%6,%7}, {%8,%9}, {%0,%1,%2,%3};"
        : "+f"(c[0]), "+f"(c[1]), "+f"(c[2]), "+f"(c[3])
        : "r"(a[0]), "r"(a[1]), "r"(a[2]), "r"(a[3]), "r"(b[0]), "r"(b[1]));
}

__device__ __forceinline__ void edge_pair(const void* ei, int e, int& src, int& dst) {
    if (g_ei_is64) {
        const long long* e64 = (const long long*)ei;
        src = (int)e64[e];
        dst = (int)e64[NEDGES + e];
    } else {
        const int* e32 = (const int*)ei;
        src = e32[e];
        dst = e32[NEDGES + e];
    }
}

// ---------------------------------------------------------------------------
// Kernel 0: detect edge_index dtype (int64 -> odd int32 words all zero)
// ---------------------------------------------------------------------------
__global__ void detect_kernel(const int* __restrict__ ei32) {
    if (threadIdx.x == 0 && blockIdx.x == 0) {
        int acc = 0;
#pragma unroll
        for (int i = 1; i < 32; i += 2) acc |= ei32[i];
        g_ei_is64 = (acc == 0) ? 1 : 0;
    }
}

// ---------------------------------------------------------------------------
// Kernel 1: zero degree counters
// ---------------------------------------------------------------------------
__global__ void zero_deg_kernel() {
    const int i = blockIdx.x * blockDim.x + threadIdx.x;
    if (i < NNODES) g_degi[i] = 0;
}

// ---------------------------------------------------------------------------
// Kernel 2: degree count
// ---------------------------------------------------------------------------
__global__ __launch_bounds__(256) void degcount_kernel(const void* __restrict__ ei) {
    const int e = blockIdx.x * blockDim.x + threadIdx.x;
    if (e >= NEDGES) return;
    int src, dst;
    edge_pair(ei, e, src, dst);
    if ((unsigned)src >= NNODES || (unsigned)dst >= NNODES) return;
    atomicAdd(&g_degi[dst], 1);
}

// ---------------------------------------------------------------------------
// Kernel 3: single-block exclusive prefix scan over degrees
// ---------------------------------------------------------------------------
__global__ __launch_bounds__(512) void scan_kernel() {
    __shared__ int sh[512];
    __shared__ int carry;
    const int t = threadIdx.x;
    if (t == 0) carry = 0;
    __syncthreads();

    for (int base = 0; base < NNODES; base += 512) {
        const int i = base + t;
        const int v = (i < NNODES) ? g_degi[i] : 0;
        sh[t] = v;
        __syncthreads();
#pragma unroll
        for (int off = 1; off < 512; off <<= 1) {
            int u = (t >= off) ? sh[t - off] : 0;
            __syncthreads();
            sh[t] += u;
            __syncthreads();
        }
        if (i < NNODES) {
            const int ex = carry + sh[t] - v;
            g_off[i] = ex;
            g_cursor[i] = ex;
        }
        __syncthreads();
        if (t == 0) carry += sh[511];
        __syncthreads();
    }
    if (t == 0) g_off[NNODES] = carry;
}

// ---------------------------------------------------------------------------
// Kernel 4: fill CSR edge list
// ---------------------------------------------------------------------------
__global__ __launch_bounds__(256) void fill_kernel(const void* __restrict__ ei) {
    const int e = blockIdx.x * blockDim.x + threadIdx.x;
    if (e >= NEDGES) return;
    int src, dst;
    edge_pair(ei, e, src, dst);
    if ((unsigned)src >= NNODES || (unsigned)dst >= NNODES) return;
    const int pos = atomicAdd(&g_cursor[dst], 1);
    g_elist[pos] = src;
}

// ---------------------------------------------------------------------------
// Kernel 5: gather + mean + bf16 hi/lo split  (cols [0,512) of A)
// one warp per (node, 128-col slice)
// ---------------------------------------------------------------------------
__global__ __launch_bounds__(256) void gatherA_kernel(const float* __restrict__ x) {
    const int gw   = (blockIdx.x * blockDim.x + threadIdx.x) >> 5;
    const int lane = threadIdx.x & 31;
    if (gw >= NNODES * 4) return;
    const int node  = gw >> 2;
    const int slice = gw & 3;
    const int beg = g_off[node];
    const int end = g_off[node + 1];

    const float* xb = x + slice * 128 + lane * 4;
    float4 acc = make_float4(0.f, 0.f, 0.f, 0.f);
    for (int e = beg; e < end; ++e) {
        const int src = g_elist[e];
        const float4 v = *(const float4*)(xb + (size_t)src * DDIM);
        acc.x += v.x; acc.y += v.y; acc.z += v.z; acc.w += v.w;
    }
    const float invd = 1.0f / fmaxf((float)(end - beg), 1.0f);
    acc.x *= invd; acc.y *= invd; acc.z *= invd; acc.w *= invd;

    __nv_bfloat162 h01 = __float22bfloat162_rn(make_float2(acc.x, acc.y));
    __nv_bfloat162 h23 = __float22bfloat162_rn(make_float2(acc.z, acc.w));
    __nv_bfloat162 l01 = __float22bfloat162_rn(make_float2(
        acc.x - __bfloat162float(__low2bfloat16(h01)),
        acc.y - __bfloat162float(__high2bfloat16(h01))));
    __nv_bfloat162 l23 = __float22bfloat162_rn(make_float2(
        acc.z - __bfloat162float(__low2bfloat16(h23)),
        acc.w - __bfloat162float(__high2bfloat16(h23))));

    const size_t o = (size_t)node * KTOT + slice * 128 + lane * 4;
    *(__nv_bfloat162*)(g_Ahi + o)     = h01;
    *(__nv_bfloat162*)(g_Ahi + o + 2) = h23;
    *(__nv_bfloat162*)(g_Alo + o)     = l01;
    *(__nv_bfloat162*)(g_Alo + o + 2) = l23;
}

// ---------------------------------------------------------------------------
// Kernel 6: x -> bf16 hi/lo  (cols [512,1024) of A)
// ---------------------------------------------------------------------------
__global__ __launch_bounds__(256) void convertX_kernel(const float* __restrict__ x) {
    const int i = blockIdx.x * blockDim.x + threadIdx.x;   // per 4 elems
    if (i >= NNODES * 128) return;
    const int row = i >> 7;
    const int g   = (i & 127) * 4;
    const float4 v = *(const float4*)(x + (size_t)row * DDIM + g);

    __nv_bfloat162 h01 = __float22bfloat162_rn(make_float2(v.x, v.y));
    __nv_bfloat162 h23 = __float22bfloat162_rn(make_float2(v.z, v.w));
    __nv_bfloat162 l01 = __float22bfloat162_rn(make_float2(
        v.x - __bfloat162float(__low2bfloat16(h01)),
        v.y - __bfloat162float(__high2bfloat16(h01))));
    __nv_bfloat162 l23 = __float22bfloat162_rn(make_float2(
        v.z - __bfloat162float(__low2bfloat16(h23)),
        v.w - __bfloat162float(__high2bfloat16(h23))));

    const size_t o = (size_t)row * KTOT + DDIM + g;
    *(__nv_bfloat162*)(g_Ahi + o)     = h01;
    *(__nv_bfloat162*)(g_Ahi + o + 2) = h23;
    *(__nv_bfloat162*)(g_Alo + o)     = l01;
    *(__nv_bfloat162*)(g_Alo + o + 2) = l23;
}

// ---------------------------------------------------------------------------
// Kernel 7: zero pad rows [NNODES, MPAD)
// ---------------------------------------------------------------------------
__global__ __launch_bounds__(256) void padA_kernel() {
    const int i = blockIdx.x * blockDim.x + threadIdx.x;   // per 4 elems
    if (i >= (MPAD - NNODES) * (KTOT / 4)) return;
    const int row = NNODES + (i >> 8);
    const int g   = (i & 255) * 4;
    const size_t o = (size_t)row * KTOT + g;
    *(uint64_t*)(g_Ahi + o) = 0ull;
    *(uint64_t*)(g_Alo + o) = 0ull;
}

// ---------------------------------------------------------------------------
// Kernel 8: B[n][k] = W[k][n] (W=[Wl;Wr]) -> bf16 hi/lo transposed
// ---------------------------------------------------------------------------
__global__ __launch_bounds__(256) void convertB_kernel(
    const float* __restrict__ Wl, const float* __restrict__ Wr)
{
    const int i = blockIdx.x * blockDim.x + threadIdx.x;
    if (i >= KTOT * DDIM) return;
    const int k = i >> 9;
    const int n = i & 511;
    const float w = (k < DDIM) ? Wl[(size_t)k * DDIM + n]
                               : Wr[(size_t)(k - DDIM) * DDIM + n];
    const __nv_bfloat16 hi = __float2bfloat16(w);
    const __nv_bfloat16 lo = __float2bfloat16(w - __bfloat162float(hi));
    g_Bhi[(size_t)n * KTOT + k] = hi;
    g_Blo[(size_t)n * KTOT + k] = lo;
}

// ---------------------------------------------------------------------------
// Kernel 9: HMMA GEMM (split bf16) 160x128 tile, 4-stage cp.async + swish
// ---------------------------------------------------------------------------
__device__ __forceinline__ void load_stage(
    uint32_t st, int k0, int mBase, int nBase, int tid)
{
    // 2304 16B-chunks: Ahi 640 | Alo 640 | Bhi 512 | Blo 512
#pragma unroll
    for (int i = 0; i < 9; ++i) {
        const int c = tid + i * 256;
        uint32_t sm;
        const __nv_bfloat16* gp;
        if (c < 1280) {
            const int mat = c >> 9 >= 1 ? (c >= 640 ? 1 : 0) : (c >= 640 ? 1 : 0);
            const int rem = c - mat * 640;
            const int row = rem >> 2;
            const int ch  = rem & 3;
            sm = st + (mat ? OFF_AL : OFF_AH) + row * ROWB + ch * 16;
            gp = (mat ? g_Alo : g_Ahi) + (size_t)(mBase + row) * KTOT + k0 + ch * 8;
        } else {
            const int d   = c - 1280;
            const int mat = d >> 9;               // 0=Bhi 1=Blo
            const int rem = d & 511;
            const int row = rem >> 2;
            const int ch  = rem & 3;
            sm = st + (mat ? OFF_BL : OFF_BH) + row * ROWB + ch * 16;
            gp = (mat ? g_Blo : g_Bhi) + (size_t)(nBase + row) * KTOT + k0 + ch * 8;
        }
        CP16(sm, gp);
    }
}

__global__ __launch_bounds__(256, 1)
void gemm_kernel(const float* __restrict__ bias, float* __restrict__ out)
{
    extern __shared__ __align__(128) char smem[];
    const uint32_t smem_base = smem_u32(smem);
    const int tid   = threadIdx.x;
    const int wid   = tid >> 5;
    const int lane  = tid & 31;
    const int warpM = wid >> 2;         // 0..1 -> 80 rows
    const int warpN = wid & 3;          // 0..3 -> 32 cols
    const int mBase = blockIdx.x * MTILE;
    const int nBase = blockIdx.y * 128;

    float acc[5][4][4];
#pragma unroll
    for (int i = 0; i < 5; ++i)
#pragma unroll
        for (int j = 0; j < 4; ++j)
#pragma unroll
            for (int r = 0; r < 4; ++r) acc[i][j][r] = 0.0f;

#pragma unroll
    for (int s = 0; s < NSTAGE; ++s) {
        load_stage(smem_base + s * STAGE_BYTES, s * KCHUNK, mBase, nBase, tid);
        CP_COMMIT();
    }

    const int matA = lane >> 3;
    const int rA   = lane & 7;
    const int rowA_off = ((matA & 1) << 3) + rA;
    const int chA_off  = matA >> 1;
    const int rowB_off = ((matA >> 1) << 3) + rA;
    const int chB_off  = matA & 1;

    for (int s = 0; s < KSTEPS; ++s) {
        CP_WAIT();
        __syncthreads();

        const uint32_t st  = smem_base + (s % NSTAGE) * STAGE_BYTES;
        const uint32_t sAh = st + OFF_AH;
        const uint32_t sAl = st + OFF_AL;
        const uint32_t sBh = st + OFF_BH;
        const uint32_t sBl = st + OFF_BL;

#pragma unroll
        for (int kk = 0; kk < 2; ++kk) {
            uint32_t ah[5][4], al[5][4], bh[4][2], bl[4][2];
#pragma unroll
            for (int mt = 0; mt < 5; ++mt) {
                const int row = warpM * 80 + mt * 16 + rowA_off;
                const int ch  = kk * 2 + chA_off;
                const uint32_t a = row * ROWB + ch * 16;
                LDMX4(ah[mt][0], ah[mt][1], ah[mt][2], ah[mt][3], sAh + a);
                LDMX4(al[mt][0], al[mt][1], al[mt][2], al[mt][3], sAl + a);
            }
#pragma unroll
            for (int p = 0; p < 2; ++p) {
                const int row = warpN * 32 + p * 16 + rowB_off;
                const int ch  = kk * 2 + chB_off;
                const uint32_t a = row * ROWB + ch * 16;
                LDMX4(bh[2*p][0], bh[2*p][1], bh[2*p+1][0], bh[2*p+1][1], sBh + a);
                LDMX4(bl[2*p][0], bl[2*p][1], bl[2*p+1][0], bl[2*p+1][1], sBl + a);
            }
#pragma unroll
            for (int mt = 0; mt < 5; ++mt)
#pragma unroll
                for (int nt = 0; nt < 4; ++nt) {
                    mma_bf16(acc[mt][nt], ah[mt], bh[nt]);
                    mma_bf16(acc[mt][nt], ah[mt], bl[nt]);
                    mma_bf16(acc[mt][nt], al[mt], bh[nt]);
                }
        }

        __syncthreads();
        if (s + NSTAGE < KSTEPS)
            load_stage(st, (s + NSTAGE) * KCHUNK, mBase, nBase, tid);
        CP_COMMIT();
    }

    const int colLane = (lane & 3) * 2;
    const int rowLane = lane >> 2;
#pragma unroll
    for (int mt = 0; mt < 5; ++mt) {
#pragma unroll
        for (int nt = 0; nt < 4; ++nt) {
            const int col = nBase + warpN * 32 + nt * 8 + colLane;
            const float b0 = __ldg(bias + col);
            const float b1 = __ldg(bias + col + 1);
#pragma unroll
            for (int half = 0; half < 2; ++half) {
                const int row = mBase + warpM * 80 + mt * 16 + rowLane + half * 8;
                if (row < NNODES) {
                    float h0 = acc[mt][nt][half * 2 + 0] + b0;
                    float h1 = acc[mt][nt][half * 2 + 1] + b1;
                    float2 o;
                    o.x = h0 / (1.0f + expf(-h0));
                    o.y = h1 / (1.0f + expf(-h1));
                    *(float2*)(out + (size_t)row * DDIM + col) = o;
                }
            }
        }
    }
}

// ---------------------------------------------------------------------------
extern "C" void kernel_launch(void* const* d_in, const int* in_sizes, int n_in,
                              void* d_out, int out_size) {
    const float* x  = nullptr;
    const void*  ei = nullptr;
    const float* Wl = nullptr;
    const float* Wr = nullptr;
    const float* b  = nullptr;

    for (int i = 0; i < n_in; ++i) {
        const int s = in_sizes[i];
        if (s == NNODES * DDIM)      x  = (const float*)d_in[i];
        else if (s == 2 * NEDGES)    ei = d_in[i];
        else if (s == DDIM * DDIM) { if (!Wl) Wl = (const float*)d_in[i];
                                     else     Wr = (const float*)d_in[i]; }
        else if (s == DDIM)          b  = (const float*)d_in[i];
    }
    float* out = (float*)d_out;
    (void)out_size;

    cudaFuncSetAttribute(gemm_kernel,
        cudaFuncAttributeMaxDynamicSharedMemorySize, SMEM_TOTAL);

    detect_kernel<<<1, 32>>>((const int*)ei);
    zero_deg_kernel<<<(NNODES + 255) / 256, 256>>>();
    degcount_kernel<<<(NEDGES + 255) / 256, 256>>>(ei);
    scan_kernel<<<1, 512>>>();
    fill_kernel<<<(NEDGES + 255) / 256, 256>>>(ei);
    gatherA_kernel<<<(NNODES * 4 * 32 + 255) / 256, 256>>>(x);
    convertX_kernel<<<(NNODES * 128 + 255) / 256, 256>>>(x);
    padA_kernel<<<((MPAD - NNODES) * (KTOT / 4) + 255) / 256, 256>>>();
    convertB_kernel<<<(KTOT * DDIM + 255) / 256, 256>>>(Wl, Wr);

    dim3 grid(MTILES, NTILES);
    gemm_kernel<<<grid, 256, SMEM_TOTAL>>>(b, out);
}

// round 6
// speedup vs baseline: 3.5815x; 1.0967x over previous
#include <cuda_runtime.h>
#include <cuda_bf16.h>
#include <math.h>
#include <cstdint>

#define NNODES 10000
#define NEDGES 160000
#define DDIM   512
#define KTOT   1024
#define MTILE  160
#define MTILES 64
#define MPAD   (MTILE * MTILES)   // 10240
#define NTILES 4
#define KCHUNK 32
#define NSTAGE 5
#define KSTEPS (KTOT / KCHUNK)    // 32

// smem: rows of 32 bf16, stride 80B (64B data + 16B pad) -> conflict-free LDSM
#define ROWB    80
#define A_TILEB (MTILE * ROWB)            // 12800
#define B_TILEB (128 * ROWB)              // 10240
#define OFF_AH  0
#define OFF_AL  (A_TILEB)
#define OFF_BH  (2 * A_TILEB)
#define OFF_BL  (2 * A_TILEB + B_TILEB)
#define STAGE_BYTES (2 * A_TILEB + 2 * B_TILEB)   // 46080
#define SMEM_TOTAL  (NSTAGE * STAGE_BYTES)        // 230400

// ---------------------------------------------------------------------------
// Device scratch
// ---------------------------------------------------------------------------
__device__ int   g_ei_is64;
__device__ int   g_degi[NNODES];
__device__ int   g_off[NNODES + 1];
__device__ int   g_cursor[NNODES];
__device__ int   g_elist[NEDGES];
__device__ __nv_bfloat16 g_Ahi[(size_t)MPAD * KTOT];
__device__ __nv_bfloat16 g_Alo[(size_t)MPAD * KTOT];
__device__ __nv_bfloat16 g_Bhi[(size_t)DDIM * KTOT];   // [n][k]
__device__ __nv_bfloat16 g_Blo[(size_t)DDIM * KTOT];

// ---------------------------------------------------------------------------
// helpers
// ---------------------------------------------------------------------------
__device__ __forceinline__ uint32_t smem_u32(const void* p) {
    uint32_t a;
    asm("{ .reg .u64 t; cvta.to.shared.u64 t, %1; cvt.u32.u64 %0, t; }"
        : "=r"(a) : "l"(p));
    return a;
}
#define CP16(sm, gm) \
    asm volatile("cp.async.cg.shared.global [%0], [%1], 16;" :: "r"(sm), "l"(gm))
#define CP_COMMIT() asm volatile("cp.async.commit_group;" ::: "memory")
#define CP_WAIT()   asm volatile("cp.async.wait_group 4;"  ::: "memory")

#define LDMX4(r0, r1, r2, r3, addr) \
    asm volatile("ldmatrix.sync.aligned.m8n8.x4.shared.b16 {%0,%1,%2,%3}, [%4];" \
        : "=r"(r0), "=r"(r1), "=r"(r2), "=r"(r3) : "r"(addr))

__device__ __forceinline__ void mma_bf16(float* c, const uint32_t* a,
                                         const uint32_t* b) {
    asm volatile(
        "mma.sync.aligned.m16n8k16.row.col.f32.bf16.bf16.f32 "
        "{%0,%1,%2,%3}, {%4,%5,%6,%7}, {%8,%9}, {%0,%1,%2,%3};"
        : "+f"(c[0]), "+f"(c[1]), "+f"(c[2]), "+f"(c[3])
        : "r"(a[0]), "r"(a[1]), "r"(a[2]), "r"(a[3]), "r"(b[0]), "r"(b[1]));
}

__device__ __forceinline__ void edge_pair(const void* ei, int e, int& src, int& dst) {
    if (g_ei_is64) {
        const long long* e64 = (const long long*)ei;
        src = (int)e64[e];
        dst = (int)e64[NEDGES + e];
    } else {
        const int* e32 = (const int*)ei;
        src = e32[e];
        dst = e32[NEDGES + e];
    }
}

__device__ __forceinline__ void split_store(
    float4 v, __nv_bfloat16* hi, __nv_bfloat16* lo)
{
    __nv_bfloat162 h01 = __float22bfloat162_rn(make_float2(v.x, v.y));
    __nv_bfloat162 h23 = __float22bfloat162_rn(make_float2(v.z, v.w));
    __nv_bfloat162 l01 = __float22bfloat162_rn(make_float2(
        v.x - __bfloat162float(__low2bfloat16(h01)),
        v.y - __bfloat162float(__high2bfloat16(h01))));
    __nv_bfloat162 l23 = __float22bfloat162_rn(make_float2(
        v.z - __bfloat162float(__low2bfloat16(h23)),
        v.w - __bfloat162float(__high2bfloat16(h23))));
    *(__nv_bfloat162*)(hi)     = h01;
    *(__nv_bfloat162*)(hi + 2) = h23;
    *(__nv_bfloat162*)(lo)     = l01;
    *(__nv_bfloat162*)(lo + 2) = l23;
}

// ---------------------------------------------------------------------------
// Kernel 1: detect dtype + zero degree counters
// ---------------------------------------------------------------------------
__global__ void zero_detect_kernel(const int* __restrict__ ei32) {
    const int i = blockIdx.x * blockDim.x + threadIdx.x;
    if (i == 0) {
        int acc = 0;
#pragma unroll
        for (int j = 1; j < 32; j += 2) acc |= ei32[j];
        g_ei_is64 = (acc == 0) ? 1 : 0;
    }
    if (i < NNODES) g_degi[i] = 0;
}

// ---------------------------------------------------------------------------
// Kernel 2: degree count
// ---------------------------------------------------------------------------
__global__ __launch_bounds__(256) void degcount_kernel(const void* __restrict__ ei) {
    const int e = blockIdx.x * blockDim.x + threadIdx.x;
    if (e >= NEDGES) return;
    int src, dst;
    edge_pair(ei, e, src, dst);
    if ((unsigned)src >= NNODES || (unsigned)dst >= NNODES) return;
    atomicAdd(&g_degi[dst], 1);
}

// ---------------------------------------------------------------------------
// Kernel 3: fast single-block scan: 512 threads x 20 serial elements,
// shuffle-based scan of the 512 partials.
// ---------------------------------------------------------------------------
#define SCAN_PER 20
__global__ __launch_bounds__(512) void scan_kernel() {
    __shared__ int warpSums[16];
    const int t    = threadIdx.x;
    const int lane = t & 31;
    const int warp = t >> 5;

    int v[SCAN_PER];
    int sum = 0;
    const int base = t * SCAN_PER;
#pragma unroll
    for (int j = 0; j < SCAN_PER; ++j) {
        const int i = base + j;
        v[j] = (i < NNODES) ? g_degi[i] : 0;
        sum += v[j];
    }

    // inclusive warp scan of per-thread sums
    int ws = sum;
#pragma unroll
    for (int off = 1; off < 32; off <<= 1) {
        int u = __shfl_up_sync(0xFFFFFFFF, ws, off);
        if (lane >= off) ws += u;
    }
    if (lane == 31) warpSums[warp] = ws;
    __syncthreads();

    if (warp == 0) {
        int s = (lane < 16) ? warpSums[lane] : 0;
#pragma unroll
        for (int off = 1; off < 16; off <<= 1) {
            int u = __shfl_up_sync(0xFFFFFFFF, s, off);
            if (lane >= off) s += u;
        }
        if (lane < 16) warpSums[lane] = s;
    }
    __syncthreads();

    int prefix = ws - sum;                       // exclusive within warp
    if (warp > 0) prefix += warpSums[warp - 1];  // add preceding warps

#pragma unroll
    for (int j = 0; j < SCAN_PER; ++j) {
        const int i = base + j;
        if (i < NNODES) {
            g_off[i]    = prefix;
            g_cursor[i] = prefix;
        }
        prefix += v[j];
    }
    if (t == 511) g_off[NNODES] = prefix;
}

// ---------------------------------------------------------------------------
// Kernel 4: fill CSR edge list
// ---------------------------------------------------------------------------
__global__ __launch_bounds__(256) void fill_kernel(const void* __restrict__ ei) {
    const int e = blockIdx.x * blockDim.x + threadIdx.x;
    if (e >= NEDGES) return;
    int src, dst;
    edge_pair(ei, e, src, dst);
    if ((unsigned)src >= NNODES || (unsigned)dst >= NNODES) return;
    const int pos = atomicAdd(&g_cursor[dst], 1);
    g_elist[pos] = src;
}

// ---------------------------------------------------------------------------
// Kernel 5: fused convert — block-range dispatch:
//   [0, 5000)      gather+mean+split  (A cols [0,512))
//   [5000, 10000)  x -> hi/lo         (A cols [512,1024))
//   [10000, 10240) zero pad rows
//   [10240, 10752) B transpose + split (32x32 smem tiles)
// ---------------------------------------------------------------------------
#define CV_GATHER_BLKS 5000
#define CV_X_BLKS      5000
#define CV_PAD_BLKS    240
#define CV_B_BLKS      512
#define CV_TOTAL (CV_GATHER_BLKS + CV_X_BLKS + CV_PAD_BLKS + CV_B_BLKS)

__global__ __launch_bounds__(256) void convert_all_kernel(
    const float* __restrict__ x,
    const float* __restrict__ Wl, const float* __restrict__ Wr)
{
    __shared__ float ts[32][33];
    const int bb  = blockIdx.x;
    const int tid = threadIdx.x;

    if (bb < CV_GATHER_BLKS) {
        // ---- gather + mean + split: one warp per (node, 128-col slice) ----
        const int gw   = bb * 8 + (tid >> 5);
        const int lane = tid & 31;
        const int node  = gw >> 2;
        const int slice = gw & 3;
        const int beg = g_off[node];
        const int end = g_off[node + 1];

        const float* xb = x + slice * 128 + lane * 4;
        float4 acc = make_float4(0.f, 0.f, 0.f, 0.f);
        for (int e = beg; e < end; ++e) {
            const int src = g_elist[e];
            const float4 v = *(const float4*)(xb + (size_t)src * DDIM);
            acc.x += v.x; acc.y += v.y; acc.z += v.z; acc.w += v.w;
        }
        const float invd = 1.0f / fmaxf((float)(end - beg), 1.0f);
        acc.x *= invd; acc.y *= invd; acc.z *= invd; acc.w *= invd;

        const size_t o = (size_t)node * KTOT + slice * 128 + lane * 4;
        split_store(acc, g_Ahi + o, g_Alo + o);
    } else if (bb < CV_GATHER_BLKS + CV_X_BLKS) {
        // ---- x -> hi/lo ----
        const int i = (bb - CV_GATHER_BLKS) * 256 + tid;  // per 4 elems
        const int row = i >> 7;
        const int g   = (i & 127) * 4;
        const float4 v = *(const float4*)(x + (size_t)row * DDIM + g);
        const size_t o = (size_t)row * KTOT + DDIM + g;
        split_store(v, g_Ahi + o, g_Alo + o);
    } else if (bb < CV_GATHER_BLKS + CV_X_BLKS + CV_PAD_BLKS) {
        // ---- zero pad rows [NNODES, MPAD) ----
        const int i = (bb - CV_GATHER_BLKS - CV_X_BLKS) * 256 + tid;
        const int row = NNODES + (i >> 8);
        const int g   = (i & 255) * 4;
        const size_t o = (size_t)row * KTOT + g;
        *(uint64_t*)(g_Ahi + o) = 0ull;
        *(uint64_t*)(g_Alo + o) = 0ull;
    } else {
        // ---- B transpose: 32(k) x 32(n) tile via smem ----
        const int tb = bb - CV_GATHER_BLKS - CV_X_BLKS - CV_PAD_BLKS;
        const int k0 = (tb >> 4) * 32;        // 0..992
        const int n0 = (tb & 15) * 32;        // 0..480
        const int r  = tid >> 3;              // 0..31
        const int c  = (tid & 7) * 4;         // 0,4,..,28

        const int k = k0 + r;
        const float4 v = (k < DDIM)
            ? *(const float4*)(Wl + (size_t)k * DDIM + n0 + c)
            : *(const float4*)(Wr + (size_t)(k - DDIM) * DDIM + n0 + c);
        ts[r][c + 0] = v.x; ts[r][c + 1] = v.y;
        ts[r][c + 2] = v.z; ts[r][c + 3] = v.w;
        __syncthreads();

        // write: row = n, 4 contiguous k
        const int n = n0 + r;
        float4 w = make_float4(ts[c][r], ts[c + 1][r], ts[c + 2][r], ts[c + 3][r]);
        const size_t o = (size_t)n * KTOT + k0 + c;
        split_store(w, g_Bhi + o, g_Blo + o);
    }
}

// ---------------------------------------------------------------------------
// Kernel 6: HMMA GEMM (split bf16) 160x128 tile, 5-stage cp.async + swish
// ---------------------------------------------------------------------------
__device__ __forceinline__ void load_stage(
    uint32_t st, int k0, int mBase, int nBase, int tid)
{
    // 2304 16B-chunks: Ahi 640 | Alo 640 | Bhi 512 | Blo 512
#pragma unroll
    for (int i = 0; i < 9; ++i) {
        const int c = tid + i * 256;
        uint32_t sm;
        const __nv_bfloat16* gp;
        if (c < 1280) {
            const int mat = (c >= 640) ? 1 : 0;
            const int rem = c - mat * 640;
            const int row = rem >> 2;
            const int ch  = rem & 3;
            sm = st + (mat ? OFF_AL : OFF_AH) + row * ROWB + ch * 16;
            gp = (mat ? g_Alo : g_Ahi) + (size_t)(mBase + row) * KTOT + k0 + ch * 8;
        } else {
            const int d   = c - 1280;
            const int mat = d >> 9;               // 0=Bhi 1=Blo
            const int rem = d & 511;
            const int row = rem >> 2;
            const int ch  = rem & 3;
            sm = st + (mat ? OFF_BL : OFF_BH) + row * ROWB + ch * 16;
            gp = (mat ? g_Blo : g_Bhi) + (size_t)(nBase + row) * KTOT + k0 + ch * 8;
        }
        CP16(sm, gp);
    }
}

__global__ __launch_bounds__(256, 1)
void gemm_kernel(const float* __restrict__ bias, float* __restrict__ out)
{
    extern __shared__ __align__(128) char smem[];
    const uint32_t smem_base = smem_u32(smem);
    const int tid   = threadIdx.x;
    const int wid   = tid >> 5;
    const int lane  = tid & 31;
    const int warpM = wid >> 2;         // 0..1 -> 80 rows
    const int warpN = wid & 3;          // 0..3 -> 32 cols
    const int mBase = blockIdx.x * MTILE;
    const int nBase = blockIdx.y * 128;

    float acc[5][4][4];
#pragma unroll
    for (int i = 0; i < 5; ++i)
#pragma unroll
        for (int j = 0; j < 4; ++j)
#pragma unroll
            for (int r = 0; r < 4; ++r) acc[i][j][r] = 0.0f;

#pragma unroll
    for (int s = 0; s < NSTAGE; ++s) {
        load_stage(smem_base + s * STAGE_BYTES, s * KCHUNK, mBase, nBase, tid);
        CP_COMMIT();
    }

    const int matA = lane >> 3;
    const int rA   = lane & 7;
    const int rowA_off = ((matA & 1) << 3) + rA;
    const int chA_off  = matA >> 1;
    const int rowB_off = ((matA >> 1) << 3) + rA;
    const int chB_off  = matA & 1;

    for (int s = 0; s < KSTEPS; ++s) {
        CP_WAIT();
        __syncthreads();

        const uint32_t st  = smem_base + (s % NSTAGE) * STAGE_BYTES;
        const uint32_t sAh = st + OFF_AH;
        const uint32_t sAl = st + OFF_AL;
        const uint32_t sBh = st + OFF_BH;
        const uint32_t sBl = st + OFF_BL;

#pragma unroll
        for (int kk = 0; kk < 2; ++kk) {
            uint32_t ah[5][4], al[5][4], bh[4][2], bl[4][2];
#pragma unroll
            for (int mt = 0; mt < 5; ++mt) {
                const int row = warpM * 80 + mt * 16 + rowA_off;
                const int ch  = kk * 2 + chA_off;
                const uint32_t a = row * ROWB + ch * 16;
                LDMX4(ah[mt][0], ah[mt][1], ah[mt][2], ah[mt][3], sAh + a);
                LDMX4(al[mt][0], al[mt][1], al[mt][2], al[mt][3], sAl + a);
            }
#pragma unroll
            for (int p = 0; p < 2; ++p) {
                const int row = warpN * 32 + p * 16 + rowB_off;
                const int ch  = kk * 2 + chB_off;
                const uint32_t a = row * ROWB + ch * 16;
                LDMX4(bh[2*p][0], bh[2*p][1], bh[2*p+1][0], bh[2*p+1][1], sBh + a);
                LDMX4(bl[2*p][0], bl[2*p][1], bl[2*p+1][0], bl[2*p+1][1], sBl + a);
            }
#pragma unroll
            for (int mt = 0; mt < 5; ++mt)
#pragma unroll
                for (int nt = 0; nt < 4; ++nt) {
                    mma_bf16(acc[mt][nt], ah[mt], bh[nt]);
                    mma_bf16(acc[mt][nt], ah[mt], bl[nt]);
                    mma_bf16(acc[mt][nt], al[mt], bh[nt]);
                }
        }

        __syncthreads();
        if (s + NSTAGE < KSTEPS)
            load_stage(st, (s + NSTAGE) * KCHUNK, mBase, nBase, tid);
        CP_COMMIT();
    }

    const int colLane = (lane & 3) * 2;
    const int rowLane = lane >> 2;
#pragma unroll
    for (int mt = 0; mt < 5; ++mt) {
#pragma unroll
        for (int nt = 0; nt < 4; ++nt) {
            const int col = nBase + warpN * 32 + nt * 8 + colLane;
            const float b0 = __ldg(bias + col);
            const float b1 = __ldg(bias + col + 1);
#pragma unroll
            for (int half = 0; half < 2; ++half) {
                const int row = mBase + warpM * 80 + mt * 16 + rowLane + half * 8;
                if (row < NNODES) {
                    float h0 = acc[mt][nt][half * 2 + 0] + b0;
                    float h1 = acc[mt][nt][half * 2 + 1] + b1;
                    float2 o;
                    o.x = h0 / (1.0f + expf(-h0));
                    o.y = h1 / (1.0f + expf(-h1));
                    *(float2*)(out + (size_t)row * DDIM + col) = o;
                }
            }
        }
    }
}

// ---------------------------------------------------------------------------
extern "C" void kernel_launch(void* const* d_in, const int* in_sizes, int n_in,
                              void* d_out, int out_size) {
    const float* x  = nullptr;
    const void*  ei = nullptr;
    const float* Wl = nullptr;
    const float* Wr = nullptr;
    const float* b  = nullptr;

    for (int i = 0; i < n_in; ++i) {
        const int s = in_sizes[i];
        if (s == NNODES * DDIM)      x  = (const float*)d_in[i];
        else if (s == 2 * NEDGES)    ei = d_in[i];
        else if (s == DDIM * DDIM) { if (!Wl) Wl = (const float*)d_in[i];
                                     else     Wr = (const float*)d_in[i]; }
        else if (s == DDIM)          b  = (const float*)d_in[i];
    }
    float* out = (float*)d_out;
    (void)out_size;

    cudaFuncSetAttribute(gemm_kernel,
        cudaFuncAttributeMaxDynamicSharedMemorySize, SMEM_TOTAL);

    zero_detect_kernel<<<(NNODES + 255) / 256, 256>>>((const int*)ei);
    degcount_kernel<<<(NEDGES + 255) / 256, 256>>>(ei);
    scan_kernel<<<1, 512>>>();
    fill_kernel<<<(NEDGES + 255) / 256, 256>>>(ei);
    convert_all_kernel<<<CV_TOTAL, 256>>>(x, Wl, Wr);

    dim3 grid(MTILES, NTILES);
    gemm_kernel<<<grid, 256, SMEM_TOTAL>>>(b, out);
}

// round 7
// speedup vs baseline: 4.0838x; 1.1402x over previous
#include <cuda_runtime.h>
#include <cuda_bf16.h>
#include <math.h>
#include <cstdint>

#define NNODES 10000
#define NEDGES 160000
#define DDIM   512
#define KTOT   1024
#define MTILE  96
#define MTILES 105
#define MPAD   (MTILE * MTILES)   // 10080
#define KCHUNK 32
#define NSTAGE 6
#define KSTEPS (KTOT / KCHUNK)    // 32
#define DEGCAP 128                // padded CSR capacity per node

// smem rows: 32 bf16, stride 80B (64B data + 16B pad) -> conflict-free LDSM
#define ROWB    80
#define A_TILEB (MTILE * ROWB)            // 7680
#define B_TILEB (128 * ROWB)              // 10240
#define OFF_AH  0
#define OFF_AL  (A_TILEB)
#define OFF_BH  (2 * A_TILEB)
#define OFF_BL  (2 * A_TILEB + B_TILEB)
#define STAGE_BYTES (2 * A_TILEB + 2 * B_TILEB)   // 35840
#define SMEM_TOTAL  (NSTAGE * STAGE_BYTES)        // 215040

// ---------------------------------------------------------------------------
// Device scratch
// ---------------------------------------------------------------------------
__device__ int   g_ei_is64;
__device__ int   g_cursor[NNODES];
__device__ int   g_elist[(size_t)NNODES * DEGCAP];
__device__ __nv_bfloat16 g_Ahi[(size_t)MPAD * KTOT];
__device__ __nv_bfloat16 g_Alo[(size_t)MPAD * KTOT];
__device__ __nv_bfloat16 g_Bhi[(size_t)DDIM * KTOT];   // [n][k]
__device__ __nv_bfloat16 g_Blo[(size_t)DDIM * KTOT];

// ---------------------------------------------------------------------------
// helpers
// ---------------------------------------------------------------------------
__device__ __forceinline__ uint32_t smem_u32(const void* p) {
    uint32_t a;
    asm("{ .reg .u64 t; cvta.to.shared.u64 t, %1; cvt.u32.u64 %0, t; }"
        : "=r"(a) : "l"(p));
    return a;
}
#define CP16(sm, gm) \
    asm volatile("cp.async.cg.shared.global [%0], [%1], 16;" :: "r"(sm), "l"(gm))
#define CP_COMMIT() asm volatile("cp.async.commit_group;" ::: "memory")
#define CP_WAIT()   asm volatile("cp.async.wait_group 5;"  ::: "memory")

#define LDMX4(r0, r1, r2, r3, addr) \
    asm volatile("ldmatrix.sync.aligned.m8n8.x4.shared.b16 {%0,%1,%2,%3}, [%4];" \
        : "=r"(r0), "=r"(r1), "=r"(r2), "=r"(r3) : "r"(addr))

__device__ __forceinline__ void mma_bf16(float* c, const uint32_t* a,
                                         const uint32_t* b) {
    asm volatile(
        "mma.sync.aligned.m16n8k16.row.col.f32.bf16.bf16.f32 "
        "{%0,%1,%2,%3}, {%4,%5,%6,%7}, {%8,%9}, {%0,%1,%2,%3};"
        : "+f"(c[0]), "+f"(c[1]), "+f"(c[2]), "+f"(c[3])
        : "r"(a[0]), "r"(a[1]), "r"(a[2]), "r"(a[3]), "r"(b[0]), "r"(b[1]));
}

__device__ __forceinline__ void edge_pair(const void* ei, int e, int& src, int& dst) {
    if (g_ei_is64) {
        const long long* e64 = (const long long*)ei;
        src = (int)e64[e];
        dst = (int)e64[NEDGES + e];
    } else {
        const int* e32 = (const int*)ei;
        src = e32[e];
        dst = e32[NEDGES + e];
    }
}

__device__ __forceinline__ void split_store(
    float4 v, __nv_bfloat16* hi, __nv_bfloat16* lo)
{
    __nv_bfloat162 h01 = __float22bfloat162_rn(make_float2(v.x, v.y));
    __nv_bfloat162 h23 = __float22bfloat162_rn(make_float2(v.z, v.w));
    __nv_bfloat162 l01 = __float22bfloat162_rn(make_float2(
        v.x - __bfloat162float(__low2bfloat16(h01)),
        v.y - __bfloat162float(__high2bfloat16(h01))));
    __nv_bfloat162 l23 = __float22bfloat162_rn(make_float2(
        v.z - __bfloat162float(__low2bfloat16(h23)),
        v.w - __bfloat162float(__high2bfloat16(h23))));
    *(__nv_bfloat162*)(hi)     = h01;
    *(__nv_bfloat162*)(hi + 2) = h23;
    *(__nv_bfloat162*)(lo)     = l01;
    *(__nv_bfloat162*)(lo + 2) = l23;
}

// ---------------------------------------------------------------------------
// Kernel 1: detect dtype + zero cursors
// ---------------------------------------------------------------------------
__global__ void zero_detect_kernel(const int* __restrict__ ei32) {
    const int i = blockIdx.x * blockDim.x + threadIdx.x;
    if (i == 0) {
        int acc = 0;
#pragma unroll
        for (int j = 1; j < 32; j += 2) acc |= ei32[j];
        g_ei_is64 = (acc == 0) ? 1 : 0;
    }
    if (i < NNODES) g_cursor[i] = 0;
}

// ---------------------------------------------------------------------------
// Kernel 2: padded-CSR bucket fill (no scan needed)
// ---------------------------------------------------------------------------
__global__ __launch_bounds__(256) void fill_kernel(const void* __restrict__ ei) {
    const int e = blockIdx.x * blockDim.x + threadIdx.x;
    if (e >= NEDGES) return;
    int src, dst;
    edge_pair(ei, e, src, dst);
    if ((unsigned)src >= NNODES || (unsigned)dst >= NNODES) return;
    const int pos = atomicAdd(&g_cursor[dst], 1);
    if (pos < DEGCAP) g_elist[(size_t)dst * DEGCAP + pos] = src;
}

// ---------------------------------------------------------------------------
// Kernel 3: fused convert — block-range dispatch:
//   [0, 5000)       gather+mean+split  (A cols [0,512))
//   [5000, 10000)   x -> hi/lo         (A cols [512,1024))
//   [10000, 10080)  zero pad rows
//   [10080, 10592)  B transpose + split (32x32 smem tiles)
// ---------------------------------------------------------------------------
#define CV_GATHER_BLKS 5000
#define CV_X_BLKS      5000
#define CV_PAD_BLKS    80
#define CV_B_BLKS      512
#define CV_TOTAL (CV_GATHER_BLKS + CV_X_BLKS + CV_PAD_BLKS + CV_B_BLKS)

__global__ __launch_bounds__(256) void convert_all_kernel(
    const float* __restrict__ x,
    const float* __restrict__ Wl, const float* __restrict__ Wr)
{
    __shared__ float ts[32][33];
    const int bb  = blockIdx.x;
    const int tid = threadIdx.x;

    if (bb < CV_GATHER_BLKS) {
        // ---- gather + mean + split: one warp per (node, 128-col slice) ----
        const int gw   = bb * 8 + (tid >> 5);
        const int lane = tid & 31;
        const int node  = gw >> 2;
        const int slice = gw & 3;
        int deg = g_cursor[node];
        if (deg > DEGCAP) deg = DEGCAP;
        const int* el = g_elist + (size_t)node * DEGCAP;

        const float* xb = x + slice * 128 + lane * 4;
        float4 acc = make_float4(0.f, 0.f, 0.f, 0.f);
        for (int e = 0; e < deg; ++e) {
            const int src = el[e];
            const float4 v = *(const float4*)(xb + (size_t)src * DDIM);
            acc.x += v.x; acc.y += v.y; acc.z += v.z; acc.w += v.w;
        }
        const float invd = 1.0f / fmaxf((float)deg, 1.0f);
        acc.x *= invd; acc.y *= invd; acc.z *= invd; acc.w *= invd;

        const size_t o = (size_t)node * KTOT + slice * 128 + lane * 4;
        split_store(acc, g_Ahi + o, g_Alo + o);
    } else if (bb < CV_GATHER_BLKS + CV_X_BLKS) {
        // ---- x -> hi/lo ----
        const int i = (bb - CV_GATHER_BLKS) * 256 + tid;  // per 4 elems
        const int row = i >> 7;
        const int g   = (i & 127) * 4;
        const float4 v = *(const float4*)(x + (size_t)row * DDIM + g);
        const size_t o = (size_t)row * KTOT + DDIM + g;
        split_store(v, g_Ahi + o, g_Alo + o);
    } else if (bb < CV_GATHER_BLKS + CV_X_BLKS + CV_PAD_BLKS) {
        // ---- zero pad rows [NNODES, MPAD): 80 rows x 1024 / 4 per thread ----
        const int i = (bb - CV_GATHER_BLKS - CV_X_BLKS) * 256 + tid;
        const int row = NNODES + (i >> 8);
        const int g   = (i & 255) * 4;
        const size_t o = (size_t)row * KTOT + g;
        *(uint64_t*)(g_Ahi + o) = 0ull;
        *(uint64_t*)(g_Alo + o) = 0ull;
    } else {
        // ---- B transpose: 32(k) x 32(n) tile via smem ----
        const int tb = bb - CV_GATHER_BLKS - CV_X_BLKS - CV_PAD_BLKS;
        const int k0 = (tb >> 4) * 32;        // 0..992
        const int n0 = (tb & 15) * 32;        // 0..480
        const int r  = tid >> 3;              // 0..31
        const int c  = (tid & 7) * 4;         // 0,4,..,28

        const int k = k0 + r;
        const float4 v = (k < DDIM)
            ? *(const float4*)(Wl + (size_t)k * DDIM + n0 + c)
            : *(const float4*)(Wr + (size_t)(k - DDIM) * DDIM + n0 + c);
        ts[r][c + 0] = v.x; ts[r][c + 1] = v.y;
        ts[r][c + 2] = v.z; ts[r][c + 3] = v.w;
        __syncthreads();

        const int n = n0 + r;
        float4 w = make_float4(ts[c][r], ts[c + 1][r], ts[c + 2][r], ts[c + 3][r]);
        const size_t o = (size_t)n * KTOT + k0 + c;
        split_store(w, g_Bhi + o, g_Blo + o);
    }
}

// ---------------------------------------------------------------------------
// Kernel 4: HMMA GEMM (split bf16) 96x128 tile, 6-stage cp.async + swish
// ---------------------------------------------------------------------------
__device__ __forceinline__ void load_stage(
    uint32_t st, int k0, int mBase, int nBase, int tid)
{
    // 1792 16B-chunks: Ahi 384 | Alo 384 | Bhi 512 | Blo 512
#pragma unroll
    for (int i = 0; i < 7; ++i) {
        const int c = tid + i * 256;
        uint32_t sm;
        const __nv_bfloat16* gp;
        if (c < 768) {
            const int mat = (c >= 384) ? 1 : 0;
            const int rem = c - mat * 384;
            const int row = rem >> 2;
            const int ch  = rem & 3;
            sm = st + (mat ? OFF_AL : OFF_AH) + row * ROWB + ch * 16;
            gp = (mat ? g_Alo : g_Ahi) + (size_t)(mBase + row) * KTOT + k0 + ch * 8;
        } else {
            const int d   = c - 768;
            const int mat = d >> 9;               // 0=Bhi 1=Blo
            const int rem = d & 511;
            const int row = rem >> 2;
            const int ch  = rem & 3;
            sm = st + (mat ? OFF_BL : OFF_BH) + row * ROWB + ch * 16;
            gp = (mat ? g_Blo : g_Bhi) + (size_t)(nBase + row) * KTOT + k0 + ch * 8;
        }
        CP16(sm, gp);
    }
}

__global__ __launch_bounds__(256, 1)
void gemm_kernel(const float* __restrict__ bias, float* __restrict__ out)
{
    extern __shared__ __align__(128) char smem[];
    const uint32_t smem_base = smem_u32(smem);
    const int tid   = threadIdx.x;
    const int wid   = tid >> 5;
    const int lane  = tid & 31;
    const int warpM = wid >> 2;         // 0..1 -> 48 rows
    const int warpN = wid & 3;          // 0..3 -> 32 cols
    const int mBase = blockIdx.x * MTILE;
    const int nBase = blockIdx.y * 128;

    float acc[3][4][4];
#pragma unroll
    for (int i = 0; i < 3; ++i)
#pragma unroll
        for (int j = 0; j < 4; ++j)
#pragma unroll
            for (int r = 0; r < 4; ++r) acc[i][j][r] = 0.0f;

#pragma unroll
    for (int s = 0; s < NSTAGE; ++s) {
        load_stage(smem_base + s * STAGE_BYTES, s * KCHUNK, mBase, nBase, tid);
        CP_COMMIT();
    }

    const int matA = lane >> 3;
    const int rA   = lane & 7;
    const int rowA_off = ((matA & 1) << 3) + rA;
    const int chA_off  = matA >> 1;
    const int rowB_off = ((matA >> 1) << 3) + rA;
    const int chB_off  = matA & 1;

    for (int s = 0; s < KSTEPS; ++s) {
        CP_WAIT();
        __syncthreads();

        const uint32_t st  = smem_base + (s % NSTAGE) * STAGE_BYTES;
        const uint32_t sAh = st + OFF_AH;
        const uint32_t sAl = st + OFF_AL;
        const uint32_t sBh = st + OFF_BH;
        const uint32_t sBl = st + OFF_BL;

#pragma unroll
        for (int kk = 0; kk < 2; ++kk) {
            uint32_t ah[3][4], al[3][4], bh[4][2], bl[4][2];
#pragma unroll
            for (int mt = 0; mt < 3; ++mt) {
                const int row = warpM * 48 + mt * 16 + rowA_off;
                const int ch  = kk * 2 + chA_off;
                const uint32_t a = row * ROWB + ch * 16;
                LDMX4(ah[mt][0], ah[mt][1], ah[mt][2], ah[mt][3], sAh + a);
                LDMX4(al[mt][0], al[mt][1], al[mt][2], al[mt][3], sAl + a);
            }
#pragma unroll
            for (int p = 0; p < 2; ++p) {
                const int row = warpN * 32 + p * 16 + rowB_off;
                const int ch  = kk * 2 + chB_off;
                const uint32_t a = row * ROWB + ch * 16;
                LDMX4(bh[2*p][0], bh[2*p][1], bh[2*p+1][0], bh[2*p+1][1], sBh + a);
                LDMX4(bl[2*p][0], bl[2*p][1], bl[2*p+1][0], bl[2*p+1][1], sBl + a);
            }
#pragma unroll
            for (int mt = 0; mt < 3; ++mt)
#pragma unroll
                for (int nt = 0; nt < 4; ++nt) {
                    mma_bf16(acc[mt][nt], ah[mt], bh[nt]);
                    mma_bf16(acc[mt][nt], ah[mt], bl[nt]);
                    mma_bf16(acc[mt][nt], al[mt], bh[nt]);
                }
        }

        __syncthreads();
        if (s + NSTAGE < KSTEPS)
            load_stage(st, (s + NSTAGE) * KCHUNK, mBase, nBase, tid);
        CP_COMMIT();
    }

    const int colLane = (lane & 3) * 2;
    const int rowLane = lane >> 2;
#pragma unroll
    for (int mt = 0; mt < 3; ++mt) {
#pragma unroll
        for (int nt = 0; nt < 4; ++nt) {
            const int col = nBase + warpN * 32 + nt * 8 + colLane;
            const float b0 = __ldg(bias + col);
            const float b1 = __ldg(bias + col + 1);
#pragma unroll
            for (int half = 0; half < 2; ++half) {
                const int row = mBase + warpM * 48 + mt * 16 + rowLane + half * 8;
                if (row < NNODES) {
                    float h0 = acc[mt][nt][half * 2 + 0] + b0;
                    float h1 = acc[mt][nt][half * 2 + 1] + b1;
                    float2 o;
                    o.x = h0 / (1.0f + expf(-h0));
                    o.y = h1 / (1.0f + expf(-h1));
                    *(float2*)(out + (size_t)row * DDIM + col) = o;
                }
            }
        }
    }
}

// ---------------------------------------------------------------------------
extern "C" void kernel_launch(void* const* d_in, const int* in_sizes, int n_in,
                              void* d_out, int out_size) {
    const float* x  = nullptr;
    const void*  ei = nullptr;
    const float* Wl = nullptr;
    const float* Wr = nullptr;
    const float* b  = nullptr;

    for (int i = 0; i < n_in; ++i) {
        const int s = in_sizes[i];
        if (s == NNODES * DDIM)      x  = (const float*)d_in[i];
        else if (s == 2 * NEDGES)    ei = d_in[i];
        else if (s == DDIM * DDIM) { if (!Wl) Wl = (const float*)d_in[i];
                                     else     Wr = (const float*)d_in[i]; }
        else if (s == DDIM)          b  = (const float*)d_in[i];
    }
    float* out = (float*)d_out;
    (void)out_size;

    cudaFuncSetAttribute(gemm_kernel,
        cudaFuncAttributeMaxDynamicSharedMemorySize, SMEM_TOTAL);

    zero_detect_kernel<<<(NNODES + 255) / 256, 256>>>((const int*)ei);
    fill_kernel<<<(NEDGES + 255) / 256, 256>>>(ei);
    convert_all_kernel<<<CV_TOTAL, 256>>>(x, Wl, Wr);

    dim3 grid(MTILES, 4);
    gemm_kernel<<<grid, 256, SMEM_TOTAL>>>(b, out);
}

// round 8
// speedup vs baseline: 4.6120x; 1.1293x over previous
#include <cuda_runtime.h>
#include <cuda_bf16.h>
#include <math.h>
#include <cstdint>

#define NNODES 10000
#define NEDGES 160000
#define DDIM   512
#define KTOT   1024
#define MTILE  96
#define MTILES 105
#define MPAD   (MTILE * MTILES)   // 10080
#define KCHUNK 32
#define NSTAGE 3
#define KSTEPS (KTOT / KCHUNK)    // 32
#define DEGCAP 128                // padded CSR capacity per node

// smem rows: 32 bf16, stride 80B (64B data + 16B pad) -> conflict-free LDSM
#define ROWB    80
#define A_TILEB (MTILE * ROWB)            // 7680
#define B_TILEB (128 * ROWB)              // 10240
#define OFF_AH  0
#define OFF_AL  (A_TILEB)
#define OFF_BH  (2 * A_TILEB)
#define OFF_BL  (2 * A_TILEB + B_TILEB)
#define STAGE_BYTES (2 * A_TILEB + 2 * B_TILEB)   // 35840
#define SMEM_TOTAL  (NSTAGE * STAGE_BYTES)        // 107520  -> 2 CTAs/SM

// ---------------------------------------------------------------------------
// Device scratch
// ---------------------------------------------------------------------------
__device__ int   g_ei_is64;
__device__ int   g_cursor[NNODES];
__device__ int   g_elist[(size_t)NNODES * DEGCAP];
__device__ __nv_bfloat16 g_Ahi[(size_t)MPAD * KTOT];
__device__ __nv_bfloat16 g_Alo[(size_t)MPAD * KTOT];
__device__ __nv_bfloat16 g_Bhi[(size_t)DDIM * KTOT];   // [n][k]
__device__ __nv_bfloat16 g_Blo[(size_t)DDIM * KTOT];

// ---------------------------------------------------------------------------
// helpers
// ---------------------------------------------------------------------------
__device__ __forceinline__ uint32_t smem_u32(const void* p) {
    uint32_t a;
    asm("{ .reg .u64 t; cvta.to.shared.u64 t, %1; cvt.u32.u64 %0, t; }"
        : "=r"(a) : "l"(p));
    return a;
}
#define CP16(sm, gm) \
    asm volatile("cp.async.cg.shared.global [%0], [%1], 16;" :: "r"(sm), "l"(gm))
#define CP_COMMIT() asm volatile("cp.async.commit_group;" ::: "memory")
#define CP_WAIT()   asm volatile("cp.async.wait_group 2;"  ::: "memory")

#define LDMX4(r0, r1, r2, r3, addr) \
    asm volatile("ldmatrix.sync.aligned.m8n8.x4.shared.b16 {%0,%1,%2,%3}, [%4];" \
        : "=r"(r0), "=r"(r1), "=r"(r2), "=r"(r3) : "r"(addr))

__device__ __forceinline__ void mma_bf16(float* c, const uint32_t* a,
                                         const uint32_t* b) {
    asm volatile(
        "mma.sync.aligned.m16n8k16.row.col.f32.bf16.bf16.f32 "
        "{%0,%1,%2,%3}, {%4,%5,%6,%7}, {%8,%9}, {%0,%1,%2,%3};"
        : "+f"(c[0]), "+f"(c[1]), "+f"(c[2]), "+f"(c[3])
        : "r"(a[0]), "r"(a[1]), "r"(a[2]), "r"(a[3]), "r"(b[0]), "r"(b[1]));
}

__device__ __forceinline__ void edge_pair(const void* ei, int e, int& src, int& dst) {
    if (g_ei_is64) {
        const long long* e64 = (const long long*)ei;
        src = (int)e64[e];
        dst = (int)e64[NEDGES + e];
    } else {
        const int* e32 = (const int*)ei;
        src = e32[e];
        dst = e32[NEDGES + e];
    }
}

__device__ __forceinline__ void split_store(
    float4 v, __nv_bfloat16* hi, __nv_bfloat16* lo)
{
    __nv_bfloat162 h01 = __float22bfloat162_rn(make_float2(v.x, v.y));
    __nv_bfloat162 h23 = __float22bfloat162_rn(make_float2(v.z, v.w));
    __nv_bfloat162 l01 = __float22bfloat162_rn(make_float2(
        v.x - __bfloat162float(__low2bfloat16(h01)),
        v.y - __bfloat162float(__high2bfloat16(h01))));
    __nv_bfloat162 l23 = __float22bfloat162_rn(make_float2(
        v.z - __bfloat162float(__low2bfloat16(h23)),
        v.w - __bfloat162float(__high2bfloat16(h23))));
    *(__nv_bfloat162*)(hi)     = h01;
    *(__nv_bfloat162*)(hi + 2) = h23;
    *(__nv_bfloat162*)(lo)     = l01;
    *(__nv_bfloat162*)(lo + 2) = l23;
}

// ---------------------------------------------------------------------------
// Kernel 1: detect dtype + zero cursors
// ---------------------------------------------------------------------------
__global__ void zero_detect_kernel(const int* __restrict__ ei32) {
    const int i = blockIdx.x * blockDim.x + threadIdx.x;
    if (i == 0) {
        int acc = 0;
#pragma unroll
        for (int j = 1; j < 32; j += 2) acc |= ei32[j];
        g_ei_is64 = (acc == 0) ? 1 : 0;
    }
    if (i < NNODES) g_cursor[i] = 0;
}

// ---------------------------------------------------------------------------
// Kernel 2: padded-CSR bucket fill (no scan needed)
// ---------------------------------------------------------------------------
__global__ __launch_bounds__(256) void fill_kernel(const void* __restrict__ ei) {
    const int e = blockIdx.x * blockDim.x + threadIdx.x;
    if (e >= NEDGES) return;
    int src, dst;
    edge_pair(ei, e, src, dst);
    if ((unsigned)src >= NNODES || (unsigned)dst >= NNODES) return;
    const int pos = atomicAdd(&g_cursor[dst], 1);
    if (pos < DEGCAP) g_elist[(size_t)dst * DEGCAP + pos] = src;
}

// ---------------------------------------------------------------------------
// Kernel 3: fused convert — block-range dispatch:
//   [0, 5000)       gather+mean+split  (A cols [0,512))
//   [5000, 10000)   x -> hi/lo         (A cols [512,1024))
//   [10000, 10080)  zero pad rows
//   [10080, 10592)  B transpose + split (32x32 smem tiles)
// ---------------------------------------------------------------------------
#define CV_GATHER_BLKS 5000
#define CV_X_BLKS      5000
#define CV_PAD_BLKS    80
#define CV_B_BLKS      512
#define CV_TOTAL (CV_GATHER_BLKS + CV_X_BLKS + CV_PAD_BLKS + CV_B_BLKS)

__global__ __launch_bounds__(256) void convert_all_kernel(
    const float* __restrict__ x,
    const float* __restrict__ Wl, const float* __restrict__ Wr)
{
    __shared__ float ts[32][33];
    const int bb  = blockIdx.x;
    const int tid = threadIdx.x;

    if (bb < CV_GATHER_BLKS) {
        // ---- gather + mean + split: one warp per (node, 128-col slice) ----
        const int gw   = bb * 8 + (tid >> 5);
        const int lane = tid & 31;
        const int node  = gw >> 2;
        const int slice = gw & 3;
        int deg = g_cursor[node];
        if (deg > DEGCAP) deg = DEGCAP;
        const int* el = g_elist + (size_t)node * DEGCAP;

        const float* xb = x + slice * 128 + lane * 4;
        float4 acc = make_float4(0.f, 0.f, 0.f, 0.f);
        for (int e = 0; e < deg; ++e) {
            const int src = el[e];
            const float4 v = *(const float4*)(xb + (size_t)src * DDIM);
            acc.x += v.x; acc.y += v.y; acc.z += v.z; acc.w += v.w;
        }
        const float invd = 1.0f / fmaxf((float)deg, 1.0f);
        acc.x *= invd; acc.y *= invd; acc.z *= invd; acc.w *= invd;

        const size_t o = (size_t)node * KTOT + slice * 128 + lane * 4;
        split_store(acc, g_Ahi + o, g_Alo + o);
    } else if (bb < CV_GATHER_BLKS + CV_X_BLKS) {
        // ---- x -> hi/lo ----
        const int i = (bb - CV_GATHER_BLKS) * 256 + tid;  // per 4 elems
        const int row = i >> 7;
        const int g   = (i & 127) * 4;
        const float4 v = *(const float4*)(x + (size_t)row * DDIM + g);
        const size_t o = (size_t)row * KTOT + DDIM + g;
        split_store(v, g_Ahi + o, g_Alo + o);
    } else if (bb < CV_GATHER_BLKS + CV_X_BLKS + CV_PAD_BLKS) {
        // ---- zero pad rows [NNODES, MPAD) ----
        const int i = (bb - CV_GATHER_BLKS - CV_X_BLKS) * 256 + tid;
        const int row = NNODES + (i >> 8);
        const int g   = (i & 255) * 4;
        const size_t o = (size_t)row * KTOT + g;
        *(uint64_t*)(g_Ahi + o) = 0ull;
        *(uint64_t*)(g_Alo + o) = 0ull;
    } else {
        // ---- B transpose: 32(k) x 32(n) tile via smem ----
        const int tb = bb - CV_GATHER_BLKS - CV_X_BLKS - CV_PAD_BLKS;
        const int k0 = (tb >> 4) * 32;        // 0..992
        const int n0 = (tb & 15) * 32;        // 0..480
        const int r  = tid >> 3;              // 0..31
        const int c  = (tid & 7) * 4;         // 0,4,..,28

        const int k = k0 + r;
        const float4 v = (k < DDIM)
            ? *(const float4*)(Wl + (size_t)k * DDIM + n0 + c)
            : *(const float4*)(Wr + (size_t)(k - DDIM) * DDIM + n0 + c);
        ts[r][c + 0] = v.x; ts[r][c + 1] = v.y;
        ts[r][c + 2] = v.z; ts[r][c + 3] = v.w;
        __syncthreads();

        const int n = n0 + r;
        float4 w = make_float4(ts[c][r], ts[c + 1][r], ts[c + 2][r], ts[c + 3][r]);
        const size_t o = (size_t)n * KTOT + k0 + c;
        split_store(w, g_Bhi + o, g_Blo + o);
    }
}

// ---------------------------------------------------------------------------
// Kernel 4: HMMA GEMM (split bf16) 96x128 tile, 3-stage cp.async,
//           2 CTAs/SM co-residency + swish epilogue
// ---------------------------------------------------------------------------
__device__ __forceinline__ void load_stage(
    uint32_t st, int k0, int mBase, int nBase, int tid)
{
    // 1792 16B-chunks: Ahi 384 | Alo 384 | Bhi 512 | Blo 512
#pragma unroll
    for (int i = 0; i < 7; ++i) {
        const int c = tid + i * 256;
        uint32_t sm;
        const __nv_bfloat16* gp;
        if (c < 768) {
            const int mat = (c >= 384) ? 1 : 0;
            const int rem = c - mat * 384;
            const int row = rem >> 2;
            const int ch  = rem & 3;
            sm = st + (mat ? OFF_AL : OFF_AH) + row * ROWB + ch * 16;
            gp = (mat ? g_Alo : g_Ahi) + (size_t)(mBase + row) * KTOT + k0 + ch * 8;
        } else {
            const int d   = c - 768;
            const int mat = d >> 9;               // 0=Bhi 1=Blo
            const int rem = d & 511;
            const int row = rem >> 2;
            const int ch  = rem & 3;
            sm = st + (mat ? OFF_BL : OFF_BH) + row * ROWB + ch * 16;
            gp = (mat ? g_Blo : g_Bhi) + (size_t)(nBase + row) * KTOT + k0 + ch * 8;
        }
        CP16(sm, gp);
    }
}

__global__ __launch_bounds__(256, 2)
void gemm_kernel(const float* __restrict__ bias, float* __restrict__ out)
{
    extern __shared__ __align__(128) char smem[];
    const uint32_t smem_base = smem_u32(smem);
    const int tid   = threadIdx.x;
    const int wid   = tid >> 5;
    const int lane  = tid & 31;
    const int warpM = wid >> 2;         // 0..1 -> 48 rows
    const int warpN = wid & 3;          // 0..3 -> 32 cols
    const int mBase = blockIdx.x * MTILE;
    const int nBase = blockIdx.y * 128;

    float acc[3][4][4];
#pragma unroll
    for (int i = 0; i < 3; ++i)
#pragma unroll
        for (int j = 0; j < 4; ++j)
#pragma unroll
            for (int r = 0; r < 4; ++r) acc[i][j][r] = 0.0f;

#pragma unroll
    for (int s = 0; s < NSTAGE; ++s) {
        load_stage(smem_base + s * STAGE_BYTES, s * KCHUNK, mBase, nBase, tid);
        CP_COMMIT();
    }

    const int matA = lane >> 3;
    const int rA   = lane & 7;
    const int rowA_off = ((matA & 1) << 3) + rA;
    const int chA_off  = matA >> 1;
    const int rowB_off = ((matA >> 1) << 3) + rA;
    const int chB_off  = matA & 1;

    for (int s = 0; s < KSTEPS; ++s) {
        CP_WAIT();
        __syncthreads();

        const uint32_t st  = smem_base + (s % NSTAGE) * STAGE_BYTES;
        const uint32_t sAh = st + OFF_AH;
        const uint32_t sAl = st + OFF_AL;
        const uint32_t sBh = st + OFF_BH;
        const uint32_t sBl = st + OFF_BL;

#pragma unroll
        for (int kk = 0; kk < 2; ++kk) {
            uint32_t ah[3][4], al[3][4], bh[4][2], bl[4][2];
#pragma unroll
            for (int mt = 0; mt < 3; ++mt) {
                const int row = warpM * 48 + mt * 16 + rowA_off;
                const int ch  = kk * 2 + chA_off;
                const uint32_t a = row * ROWB + ch * 16;
                LDMX4(ah[mt][0], ah[mt][1], ah[mt][2], ah[mt][3], sAh + a);
                LDMX4(al[mt][0], al[mt][1], al[mt][2], al[mt][3], sAl + a);
            }
#pragma unroll
            for (int p = 0; p < 2; ++p) {
                const int row = warpN * 32 + p * 16 + rowB_off;
                const int ch  = kk * 2 + chB_off;
                const uint32_t a = row * ROWB + ch * 16;
                LDMX4(bh[2*p][0], bh[2*p][1], bh[2*p+1][0], bh[2*p+1][1], sBh + a);
                LDMX4(bl[2*p][0], bl[2*p][1], bl[2*p+1][0], bl[2*p+1][1], sBl + a);
            }
#pragma unroll
            for (int mt = 0; mt < 3; ++mt)
#pragma unroll
                for (int nt = 0; nt < 4; ++nt) {
                    mma_bf16(acc[mt][nt], ah[mt], bh[nt]);
                    mma_bf16(acc[mt][nt], ah[mt], bl[nt]);
                    mma_bf16(acc[mt][nt], al[mt], bh[nt]);
                }
        }

        __syncthreads();
        if (s + NSTAGE < KSTEPS)
            load_stage(st, (s + NSTAGE) * KCHUNK, mBase, nBase, tid);
        CP_COMMIT();
    }

    const int colLane = (lane & 3) * 2;
    const int rowLane = lane >> 2;
#pragma unroll
    for (int mt = 0; mt < 3; ++mt) {
#pragma unroll
        for (int nt = 0; nt < 4; ++nt) {
            const int col = nBase + warpN * 32 + nt * 8 + colLane;
            const float b0 = __ldg(bias + col);
            const float b1 = __ldg(bias + col + 1);
#pragma unroll
            for (int half = 0; half < 2; ++half) {
                const int row = mBase + warpM * 48 + mt * 16 + rowLane + half * 8;
                if (row < NNODES) {
                    float h0 = acc[mt][nt][half * 2 + 0] + b0;
                    float h1 = acc[mt][nt][half * 2 + 1] + b1;
                    float2 o;
                    o.x = h0 / (1.0f + expf(-h0));
                    o.y = h1 / (1.0f + expf(-h1));
                    *(float2*)(out + (size_t)row * DDIM + col) = o;
                }
            }
        }
    }
}

// ---------------------------------------------------------------------------
extern "C" void kernel_launch(void* const* d_in, const int* in_sizes, int n_in,
                              void* d_out, int out_size) {
    const float* x  = nullptr;
    const void*  ei = nullptr;
    const float* Wl = nullptr;
    const float* Wr = nullptr;
    const float* b  = nullptr;

    for (int i = 0; i < n_in; ++i) {
        const int s = in_sizes[i];
        if (s == NNODES * DDIM)      x  = (const float*)d_in[i];
        else if (s == 2 * NEDGES)    ei = d_in[i];
        else if (s == DDIM * DDIM) { if (!Wl) Wl = (const float*)d_in[i];
                                     else     Wr = (const float*)d_in[i]; }
        else if (s == DDIM)          b  = (const float*)d_in[i];
    }
    float* out = (float*)d_out;
    (void)out_size;

    cudaFuncSetAttribute(gemm_kernel,
        cudaFuncAttributeMaxDynamicSharedMemorySize, SMEM_TOTAL);

    zero_detect_kernel<<<(NNODES + 255) / 256, 256>>>((const int*)ei);
    fill_kernel<<<(NEDGES + 255) / 256, 256>>>(ei);
    convert_all_kernel<<<CV_TOTAL, 256>>>(x, Wl, Wr);

    dim3 grid(MTILES, 4);
    gemm_kernel<<<grid, 256, SMEM_TOTAL>>>(b, out);
}

// round 9
// speedup vs baseline: 5.9306x; 1.2859x over previous
#include <cuda_runtime.h>
#include <cuda_fp16.h>
#include <math.h>
#include <cstdint>

#define NNODES 10000
#define NEDGES 160000
#define DDIM   512
#define KTOT   1024
#define MTILE  96
#define MTILES 105
#define MPAD   (MTILE * MTILES)   // 10080
#define KCHUNK 32
#define NSTAGE 4
#define KSTEPS (KTOT / KCHUNK)    // 32
#define DEGCAP 128                // padded CSR capacity per node

// smem rows: 32 fp16, stride 80B (64B data + 16B pad) -> conflict-free LDSM
#define ROWB    80
#define A_TILEB (MTILE * ROWB)            // 7680
#define B_TILEB (128 * ROWB)              // 10240
#define OFF_AH  0
#define OFF_AL  (A_TILEB)
#define OFF_BH  (2 * A_TILEB)
#define STAGE_BYTES (2 * A_TILEB + B_TILEB)   // 25600
#define SMEM_TOTAL  (NSTAGE * STAGE_BYTES)    // 102400 -> 2 CTAs/SM

// ---------------------------------------------------------------------------
// Device scratch
// ---------------------------------------------------------------------------
__device__ int    g_cursor[NNODES];
__device__ int    g_elist[(size_t)NNODES * DEGCAP];
__device__ __half g_Ahi[(size_t)MPAD * KTOT];
__device__ __half g_Alo[(size_t)MPAD * KTOT];
__device__ __half g_Bh[(size_t)DDIM * KTOT];    // [n][k]

// ---------------------------------------------------------------------------
// helpers
// ---------------------------------------------------------------------------
__device__ __forceinline__ uint32_t smem_u32(const void* p) {
    uint32_t a;
    asm("{ .reg .u64 t; cvta.to.shared.u64 t, %1; cvt.u32.u64 %0, t; }"
        : "=r"(a) : "l"(p));
    return a;
}
#define CP16(sm, gm) \
    asm volatile("cp.async.cg.shared.global [%0], [%1], 16;" :: "r"(sm), "l"(gm))
#define CP_COMMIT() asm volatile("cp.async.commit_group;" ::: "memory")
#define CP_WAIT()   asm volatile("cp.async.wait_group 3;"  ::: "memory")

#define LDMX4(r0, r1, r2, r3, addr) \
    asm volatile("ldmatrix.sync.aligned.m8n8.x4.shared.b16 {%0,%1,%2,%3}, [%4];" \
        : "=r"(r0), "=r"(r1), "=r"(r2), "=r"(r3) : "r"(addr))

__device__ __forceinline__ void mma_fp16(float* c, const uint32_t* a,
                                         const uint32_t* b) {
    asm volatile(
        "mma.sync.aligned.m16n8k16.row.col.f32.f16.f16.f32 "
        "{%0,%1,%2,%3}, {%4,%5,%6,%7}, {%8,%9}, {%0,%1,%2,%3};"
        : "+f"(c[0]), "+f"(c[1]), "+f"(c[2]), "+f"(c[3])
        : "r"(a[0]), "r"(a[1]), "r"(a[2]), "r"(a[3]), "r"(b[0]), "r"(b[1]));
}

__device__ __forceinline__ void split_storeA(
    float4 v, __half* hi, __half* lo)
{
    __half2 h01 = __floats2half2_rn(v.x, v.y);
    __half2 h23 = __floats2half2_rn(v.z, v.w);
    __half2 l01 = __floats2half2_rn(v.x - __low2float(h01),
                                    v.y - __high2float(h01));
    __half2 l23 = __floats2half2_rn(v.z - __low2float(h23),
                                    v.w - __high2float(h23));
    *(__half2*)(hi)     = h01;
    *(__half2*)(hi + 2) = h23;
    *(__half2*)(lo)     = l01;
    *(__half2*)(lo + 2) = l23;
}

// ---------------------------------------------------------------------------
// Kernel 1: padded-CSR bucket fill (dtype detect inlined; broadcast loads)
// ---------------------------------------------------------------------------
__global__ __launch_bounds__(256) void fill_kernel(const void* __restrict__ ei) {
    const int e = blockIdx.x * blockDim.x + threadIdx.x;
    if (e >= NEDGES) return;

    const int* ei32 = (const int*)ei;
    int acc = 0;
#pragma unroll
    for (int j = 1; j < 32; j += 2) acc |= __ldg(ei32 + j);
    const bool is64 = (acc == 0);

    int src, dst;
    if (is64) {
        const long long* e64 = (const long long*)ei;
        src = (int)e64[e];
        dst = (int)e64[NEDGES + e];
    } else {
        src = ei32[e];
        dst = ei32[NEDGES + e];
    }
    if ((unsigned)src >= NNODES || (unsigned)dst >= NNODES) return;
    const int pos = atomicAdd(&g_cursor[dst], 1);
    if (pos < DEGCAP) g_elist[(size_t)dst * DEGCAP + pos] = src;
}

// ---------------------------------------------------------------------------
// Kernel 2: fused convert — block-range dispatch:
//   [0, 5000)       gather+mean+split  (A cols [0,512))
//   [5000, 10000)   x -> hi/lo         (A cols [512,1024))
//   [10000, 10080)  zero pad rows
//   [10080, 10592)  B transpose (fp16, hi only; 32x32 smem tiles)
// ---------------------------------------------------------------------------
#define CV_GATHER_BLKS 5000
#define CV_X_BLKS      5000
#define CV_PAD_BLKS    80
#define CV_B_BLKS      512
#define CV_TOTAL (CV_GATHER_BLKS + CV_X_BLKS + CV_PAD_BLKS + CV_B_BLKS)

__global__ __launch_bounds__(256) void convert_all_kernel(
    const float* __restrict__ x,
    const float* __restrict__ Wl, const float* __restrict__ Wr)
{
    __shared__ float ts[32][33];
    const int bb  = blockIdx.x;
    const int tid = threadIdx.x;

    if (bb < CV_GATHER_BLKS) {
        // ---- gather + mean + split: one warp per (node, 128-col slice) ----
        const int gw   = bb * 8 + (tid >> 5);
        const int lane = tid & 31;
        const int node  = gw >> 2;
        const int slice = gw & 3;
        int deg = g_cursor[node];
        if (deg > DEGCAP) deg = DEGCAP;
        const int* el = g_elist + (size_t)node * DEGCAP;

        const float* xb = x + slice * 128 + lane * 4;
        float4 acc = make_float4(0.f, 0.f, 0.f, 0.f);
        for (int e = 0; e < deg; ++e) {
            const int src = el[e];
            const float4 v = *(const float4*)(xb + (size_t)src * DDIM);
            acc.x += v.x; acc.y += v.y; acc.z += v.z; acc.w += v.w;
        }
        const float invd = 1.0f / fmaxf((float)deg, 1.0f);
        acc.x *= invd; acc.y *= invd; acc.z *= invd; acc.w *= invd;

        const size_t o = (size_t)node * KTOT + slice * 128 + lane * 4;
        split_storeA(acc, g_Ahi + o, g_Alo + o);
    } else if (bb < CV_GATHER_BLKS + CV_X_BLKS) {
        // ---- x -> hi/lo ----
        const int i = (bb - CV_GATHER_BLKS) * 256 + tid;  // per 4 elems
        const int row = i >> 7;
        const int g   = (i & 127) * 4;
        const float4 v = *(const float4*)(x + (size_t)row * DDIM + g);
        const size_t o = (size_t)row * KTOT + DDIM + g;
        split_storeA(v, g_Ahi + o, g_Alo + o);
    } else if (bb < CV_GATHER_BLKS + CV_X_BLKS + CV_PAD_BLKS) {
        // ---- zero pad rows [NNODES, MPAD) ----
        const int i = (bb - CV_GATHER_BLKS - CV_X_BLKS) * 256 + tid;
        const int row = NNODES + (i >> 8);
        const int g   = (i & 255) * 4;
        const size_t o = (size_t)row * KTOT + g;
        *(uint64_t*)(g_Ahi + o) = 0ull;
        *(uint64_t*)(g_Alo + o) = 0ull;
    } else {
        // ---- B transpose: 32(k) x 32(n) tile via smem, fp16 hi only ----
        const int tb = bb - CV_GATHER_BLKS - CV_X_BLKS - CV_PAD_BLKS;
        const int k0 = (tb >> 4) * 32;        // 0..992
        const int n0 = (tb & 15) * 32;        // 0..480
        const int r  = tid >> 3;              // 0..31
        const int c  = (tid & 7) * 4;         // 0,4,..,28

        const int k = k0 + r;
        const float4 v = (k < DDIM)
            ? *(const float4*)(Wl + (size_t)k * DDIM + n0 + c)
            : *(const float4*)(Wr + (size_t)(k - DDIM) * DDIM + n0 + c);
        ts[r][c + 0] = v.x; ts[r][c + 1] = v.y;
        ts[r][c + 2] = v.z; ts[r][c + 3] = v.w;
        __syncthreads();

        const int n = n0 + r;
        __half2 b01 = __floats2half2_rn(ts[c][r],     ts[c + 1][r]);
        __half2 b23 = __floats2half2_rn(ts[c + 2][r], ts[c + 3][r]);
        const size_t o = (size_t)n * KTOT + k0 + c;
        *(__half2*)(g_Bh + o)     = b01;
        *(__half2*)(g_Bh + o + 2) = b23;
    }
}

// ---------------------------------------------------------------------------
// Kernel 3: HMMA GEMM (2-term fp16 split) 96x128 tile, 4-stage cp.async,
//           2 CTAs/SM + swish epilogue. Also resets cursors for next replay.
// ---------------------------------------------------------------------------
__device__ __forceinline__ void load_stage(
    uint32_t st, int k0, int mBase, int nBase, int tid)
{
    // 1280 16B-chunks: Ahi 384 | Alo 384 | Bh 512  (exactly 5 per thread)
#pragma unroll
    for (int i = 0; i < 5; ++i) {
        const int c = tid + i * 256;
        uint32_t sm;
        const __half* gp;
        if (c < 768) {
            const int mat = (c >= 384) ? 1 : 0;
            const int rem = c - mat * 384;
            const int row = rem >> 2;
            const int ch  = rem & 3;
            sm = st + (mat ? OFF_AL : OFF_AH) + row * ROWB + ch * 16;
            gp = (mat ? g_Alo : g_Ahi) + (size_t)(mBase + row) * KTOT + k0 + ch * 8;
        } else {
            const int d   = c - 768;              // 0..511
            const int row = d >> 2;
            const int ch  = d & 3;
            sm = st + OFF_BH + row * ROWB + ch * 16;
            gp = g_Bh + (size_t)(nBase + row) * KTOT + k0 + ch * 8;
        }
        CP16(sm, gp);
    }
}

__global__ __launch_bounds__(256, 2)
void gemm_kernel(const float* __restrict__ bias, float* __restrict__ out)
{
    extern __shared__ __align__(128) char smem[];
    const uint32_t smem_base = smem_u32(smem);
    const int tid   = threadIdx.x;
    const int wid   = tid >> 5;
    const int lane  = tid & 31;
    const int warpM = wid >> 2;         // 0..1 -> 48 rows
    const int warpN = wid & 3;          // 0..3 -> 32 cols
    const int mBase = blockIdx.x * MTILE;
    const int nBase = blockIdx.y * 128;

    // reset CSR cursors for the next graph replay (gemm doesn't read them)
    if (blockIdx.y == 0 && blockIdx.x < 40) {
        const int i = blockIdx.x * 256 + tid;
        if (i < NNODES) g_cursor[i] = 0;
    }

    float acc[3][4][4];
#pragma unroll
    for (int i = 0; i < 3; ++i)
#pragma unroll
        for (int j = 0; j < 4; ++j)
#pragma unroll
            for (int r = 0; r < 4; ++r) acc[i][j][r] = 0.0f;

#pragma unroll
    for (int s = 0; s < NSTAGE; ++s) {
        load_stage(smem_base + s * STAGE_BYTES, s * KCHUNK, mBase, nBase, tid);
        CP_COMMIT();
    }

    const int matA = lane >> 3;
    const int rA   = lane & 7;
    const int rowA_off = ((matA & 1) << 3) + rA;
    const int chA_off  = matA >> 1;
    const int rowB_off = ((matA >> 1) << 3) + rA;
    const int chB_off  = matA & 1;

    for (int s = 0; s < KSTEPS; ++s) {
        CP_WAIT();
        __syncthreads();

        const uint32_t st  = smem_base + (s % NSTAGE) * STAGE_BYTES;
        const uint32_t sAh = st + OFF_AH;
        const uint32_t sAl = st + OFF_AL;
        const uint32_t sBh = st + OFF_BH;

#pragma unroll
        for (int kk = 0; kk < 2; ++kk) {
            uint32_t ah[3][4], al[3][4], bh[4][2];
#pragma unroll
            for (int mt = 0; mt < 3; ++mt) {
                const int row = warpM * 48 + mt * 16 + rowA_off;
                const int ch  = kk * 2 + chA_off;
                const uint32_t a = row * ROWB + ch * 16;
                LDMX4(ah[mt][0], ah[mt][1], ah[mt][2], ah[mt][3], sAh + a);
                LDMX4(al[mt][0], al[mt][1], al[mt][2], al[mt][3], sAl + a);
            }
#pragma unroll
            for (int p = 0; p < 2; ++p) {
                const int row = warpN * 32 + p * 16 + rowB_off;
                const int ch  = kk * 2 + chB_off;
                const uint32_t a = row * ROWB + ch * 16;
                LDMX4(bh[2*p][0], bh[2*p][1], bh[2*p+1][0], bh[2*p+1][1], sBh + a);
            }
#pragma unroll
            for (int mt = 0; mt < 3; ++mt)
#pragma unroll
                for (int nt = 0; nt < 4; ++nt) {
                    mma_fp16(acc[mt][nt], ah[mt], bh[nt]);
                    mma_fp16(acc[mt][nt], al[mt], bh[nt]);
                }
        }

        __syncthreads();
        if (s + NSTAGE < KSTEPS)
            load_stage(st, (s + NSTAGE) * KCHUNK, mBase, nBase, tid);
        CP_COMMIT();
    }

    const int colLane = (lane & 3) * 2;
    const int rowLane = lane >> 2;
#pragma unroll
    for (int mt = 0; mt < 3; ++mt) {
#pragma unroll
        for (int nt = 0; nt < 4; ++nt) {
            const int col = nBase + warpN * 32 + nt * 8 + colLane;
            const float b0 = __ldg(bias + col);
            const float b1 = __ldg(bias + col + 1);
#pragma unroll
            for (int half = 0; half < 2; ++half) {
                const int row = mBase + warpM * 48 + mt * 16 + rowLane + half * 8;
                if (row < NNODES) {
                    float h0 = acc[mt][nt][half * 2 + 0] + b0;
                    float h1 = acc[mt][nt][half * 2 + 1] + b1;
                    float2 o;
                    o.x = h0 / (1.0f + expf(-h0));
                    o.y = h1 / (1.0f + expf(-h1));
                    *(float2*)(out + (size_t)row * DDIM + col) = o;
                }
            }
        }
    }
}

// ---------------------------------------------------------------------------
extern "C" void kernel_launch(void* const* d_in, const int* in_sizes, int n_in,
                              void* d_out, int out_size) {
    const float* x  = nullptr;
    const void*  ei = nullptr;
    const float* Wl = nullptr;
    const float* Wr = nullptr;
    const float* b  = nullptr;

    for (int i = 0; i < n_in; ++i) {
        const int s = in_sizes[i];
        if (s == NNODES * DDIM)      x  = (const float*)d_in[i];
        else if (s == 2 * NEDGES)    ei = d_in[i];
        else if (s == DDIM * DDIM) { if (!Wl) Wl = (const float*)d_in[i];
                                     else     Wr = (const float*)d_in[i]; }
        else if (s == DDIM)          b  = (const float*)d_in[i];
    }
    float* out = (float*)d_out;
    (void)out_size;

    cudaFuncSetAttribute(gemm_kernel,
        cudaFuncAttributeMaxDynamicSharedMemorySize, SMEM_TOTAL);

    fill_kernel<<<(NEDGES + 255) / 256, 256>>>(ei);
    convert_all_kernel<<<CV_TOTAL, 256>>>(x, Wl, Wr);

    dim3 grid(MTILES, 4);
    gemm_kernel<<<grid, 256, SMEM_TOTAL>>>(b, out);
}